// round 13
// baseline (speedup 1.0000x reference)
#include <cuda_runtime.h>
#include <math.h>
#include <stdint.h>

#define BB 4
#define TT 2048
#define EE 1024
#define HSZ 64
#define NHEAD 16
#define MT (BB*TT)

// Scratch (allocation-free rule: device globals)
// g_q: [MT][64] tf32, hs-cols fragment-permuted, PRE-SCALED by 0.125 (exact pow2)
// g_k: [MT][64] tf32, hs-cols fragment-permuted
// g_v: [BB][64][2048] = v^T per batch, token-cols fragment-permuted, tf32
__device__ float g_q[MT*HSZ];
__device__ float g_k[MT*HSZ];
__device__ float g_v[MT*HSZ];
__device__ float g_wt[192*EE];        // packed [n][k]: Wq^T | Wk^T | Wv^T
__device__ float g_wpsumT[EE*HSZ];    // [f][h] = sum_n Wp[n*64+h][f]
__device__ float g_qkvp[2*MT*192];    // qkv split-K(2) partials
__device__ int   g_flag[128];         // per-m-tile completion counters
__device__ float g_po[4*MT*HSZ];      // attn split-k partial O (unnormalized)
__device__ float g_pm[4*MT];          // attn partial row max
__device__ float g_pl[4*MT];          // attn partial row sum

// ---------------- HMMA helpers (baseline PTX, no 'a'-suffix features) -------
__device__ __forceinline__ uint32_t f2tf(float f) {
    uint32_t r; asm("cvt.rna.tf32.f32 %0, %1;" : "=r"(r) : "f"(f)); return r;
}
__device__ __forceinline__ float f2tff(float f) { return __uint_as_float(f2tf(f)); }
__device__ __forceinline__ void mma1688(float d[4], uint32_t a0, uint32_t a1,
                                        uint32_t a2, uint32_t a3,
                                        uint32_t b0, uint32_t b1) {
    asm volatile(
        "mma.sync.aligned.m16n8k8.row.col.f32.tf32.tf32.f32 "
        "{%0,%1,%2,%3},{%4,%5,%6,%7},{%8,%9},{%0,%1,%2,%3};"
        : "+f"(d[0]), "+f"(d[1]), "+f"(d[2]), "+f"(d[3])
        : "r"(a0), "r"(a1), "r"(a2), "r"(a3), "r"(b0), "r"(b1));
}
__device__ __forceinline__ uint32_t smem_u32(const void* p) {
    uint32_t a;
    asm("{ .reg .u64 t; cvta.to.shared.u64 t, %1; cvt.u32.u64 %0, t; }" : "=r"(a) : "l"(p));
    return a;
}
#define CP16(dst, src) asm volatile("cp.async.cg.shared.global [%0], [%1], 16;" :: "r"(dst), "l"(src) : "memory")
#define CP_COMMIT()    asm volatile("cp.async.commit_group;" ::: "memory")
#define CP_WAIT0()     asm volatile("cp.async.wait_group 0;" ::: "memory")

#define ASTR 36   // GEMM smem row stride for K=32 tiles
#define OSTR 68   // out_mm smem row stride for K=64 tiles

// fragment-permute within an 8-group: col c -> 2*(c&3) + (c>>2)
__device__ __forceinline__ int perm8(int c) { return 2 * (c & 3) + (c >> 2); }

// ---------------------------------------------------------------------------
// prep (fused): blocks 0..767 pack W^T; 768..831 wpsumT (coalesced);
// block 768 also zeroes the qkv completion flags (graph-replay safe).
// ---------------------------------------------------------------------------
__global__ __launch_bounds__(256) void prep_kernel(const float* __restrict__ Wq,
                                                   const float* __restrict__ Wk,
                                                   const float* __restrict__ Wv,
                                                   const float* __restrict__ Wp)
{
    __shared__ float st[64 * 20];
    int bx = blockIdx.x, tid = threadIdx.x;
    if (bx < 768) {
        int idx = bx * 256 + tid;
        int n = idx >> 10, k = idx & 1023;
        float v = (n < 64) ? Wq[k * 64 + n] : (n < 128) ? Wk[k * 64 + (n - 64)] : Wv[k * 64 + (n - 128)];
        g_wt[idx] = v;
        return;
    }
    if (bx == 768 && tid < 128) g_flag[tid] = 0;
    const int f0 = (bx - 768) * 16;
    {
        int sub = tid >> 6, h = tid & 63;
        float4 s = make_float4(0.f, 0.f, 0.f, 0.f);
        #pragma unroll
        for (int n = 0; n < 16; n++) {
            float4 v = *(const float4*)&Wp[(size_t)(n * 64 + h) * EE + f0 + sub * 4];
            s.x += v.x; s.y += v.y; s.z += v.z; s.w += v.w;
        }
        *(float4*)&st[h * 20 + sub * 4] = s;
    }
    __syncthreads();
    {
        int fl = tid >> 4, h4 = (tid & 15) * 4;
        float4 o = make_float4(st[(h4 + 0) * 20 + fl], st[(h4 + 1) * 20 + fl],
                               st[(h4 + 2) * 20 + fl], st[(h4 + 3) * 20 + fl]);
        *(float4*)&g_wpsumT[(size_t)(f0 + fl) * HSZ + h4] = o;
    }
}

// ---------------------------------------------------------------------------
// qkv via HMMA tf32, SPLIT-K(2), 2-stage pipeline, FUSED REDUCTION EPILOGUE.
// [64 x 512] @ [512 x 192] per CTA, grid (128,2).
// Last-arriving CTA per m-tile adds the other partial (own is in regs),
// rounds to tf32, applies fragment permutes (+ q pre-scale) and the v
// transpose, writing g_q/g_k/g_v directly.  fp add commutative -> result
// independent of arrival order.
// ---------------------------------------------------------------------------
#define QSTG 9216                     // floats per stage: A 64*36 + B 192*36
#define QKV_SMEM (2 * QSTG * 4)       // 73728 B
__global__ __launch_bounds__(256) void qkv_mm(const float* __restrict__ x)
{
    extern __shared__ float smq[];
    __shared__ int islast;

    const int tid = threadIdx.x, lane = tid & 31, wid = tid >> 5;
    const int qr = lane >> 2, qc = lane & 3;
    const int wm = wid & 1, wn = wid >> 1;
    const int m0 = blockIdx.x * 64;
    const int kbase = blockIdx.y * 512;

    const int fr2 = tid >> 3, fkq = tid & 7;

    float4 aR[2], bR[6];

    #pragma unroll
    for (int i = 0; i < 2; i++) {
        int r = i * 32 + fr2;
        aR[i] = *(const float4*)&x[(size_t)(m0 + r) * EE + kbase + fkq * 4];
    }
    #pragma unroll
    for (int i = 0; i < 6; i++) {
        int r = i * 32 + fr2;
        bR[i] = *(const float4*)&g_wt[(size_t)r * EE + kbase + fkq * 4];
    }
    {
        float* D = smq;
        #pragma unroll
        for (int i = 0; i < 2; i++) {
            int r = i * 32 + fr2;
            uint32_t* s = (uint32_t*)&D[r * ASTR + (fkq >> 1) * 8 + (fkq & 1)];
            s[0] = f2tf(aR[i].x); s[2] = f2tf(aR[i].y);
            s[4] = f2tf(aR[i].z); s[6] = f2tf(aR[i].w);
        }
        #pragma unroll
        for (int i = 0; i < 6; i++) {
            int r = i * 32 + fr2;
            uint32_t* s = (uint32_t*)&D[2304 + r * ASTR + (fkq >> 1) * 8 + (fkq & 1)];
            s[0] = f2tf(bR[i].x); s[2] = f2tf(bR[i].y);
            s[4] = f2tf(bR[i].z); s[6] = f2tf(bR[i].w);
        }
    }
    #pragma unroll
    for (int i = 0; i < 2; i++) {
        int r = i * 32 + fr2;
        aR[i] = *(const float4*)&x[(size_t)(m0 + r) * EE + kbase + 32 + fkq * 4];
    }
    #pragma unroll
    for (int i = 0; i < 6; i++) {
        int r = i * 32 + fr2;
        bR[i] = *(const float4*)&g_wt[(size_t)r * EE + kbase + 32 + fkq * 4];
    }
    __syncthreads();

    float d[2][6][4] = {};

    for (int kt = 0; kt < 16; kt++) {
        float* S = smq + (kt & 1) * QSTG;

        if (kt < 15) {
            float* D = smq + ((kt & 1) ^ 1) * QSTG;
            #pragma unroll
            for (int i = 0; i < 2; i++) {
                int r = i * 32 + fr2;
                uint32_t* s = (uint32_t*)&D[r * ASTR + (fkq >> 1) * 8 + (fkq & 1)];
                s[0] = f2tf(aR[i].x); s[2] = f2tf(aR[i].y);
                s[4] = f2tf(aR[i].z); s[6] = f2tf(aR[i].w);
            }
            #pragma unroll
            for (int i = 0; i < 6; i++) {
                int r = i * 32 + fr2;
                uint32_t* s = (uint32_t*)&D[2304 + r * ASTR + (fkq >> 1) * 8 + (fkq & 1)];
                s[0] = f2tf(bR[i].x); s[2] = f2tf(bR[i].y);
                s[4] = f2tf(bR[i].z); s[6] = f2tf(bR[i].w);
            }
            if (kt < 14) {
                int k0 = kbase + (kt + 2) * 32;
                #pragma unroll
                for (int i = 0; i < 2; i++) {
                    int r = i * 32 + fr2;
                    aR[i] = *(const float4*)&x[(size_t)(m0 + r) * EE + k0 + fkq * 4];
                }
                #pragma unroll
                for (int i = 0; i < 6; i++) {
                    int r = i * 32 + fr2;
                    bR[i] = *(const float4*)&g_wt[(size_t)r * EE + k0 + fkq * 4];
                }
            }
        }

        #pragma unroll
        for (int g = 0; g < 4; g++) {
            uint32_t af[2][4];
            #pragma unroll
            for (int mi = 0; mi < 2; mi++) {
                uint2 lo = *(const uint2*)&S[(wm * 32 + mi * 16 + qr) * ASTR + g * 8 + 2 * qc];
                uint2 hi = *(const uint2*)&S[(wm * 32 + mi * 16 + qr + 8) * ASTR + g * 8 + 2 * qc];
                af[mi][0] = lo.x; af[mi][1] = hi.x; af[mi][2] = lo.y; af[mi][3] = hi.y;
            }
            #pragma unroll
            for (int ni = 0; ni < 6; ni++) {
                uint2 bf = *(const uint2*)&S[2304 + (wn * 48 + ni * 8 + qr) * ASTR + g * 8 + 2 * qc];
                mma1688(d[0][ni], af[0][0], af[0][1], af[0][2], af[0][3], bf.x, bf.y);
                mma1688(d[1][ni], af[1][0], af[1][1], af[1][2], af[1][3], bf.x, bf.y);
            }
        }
        __syncthreads();
    }

    // ---- store own partial, then elect last CTA ----
    float* pp = g_qkvp + (size_t)blockIdx.y * MT * 192;
    #pragma unroll
    for (int mi = 0; mi < 2; mi++) {
        #pragma unroll
        for (int ni = 0; ni < 6; ni++) {
            int n = wn * 48 + ni * 8 + 2 * qc;
            int r = m0 + wm * 32 + mi * 16 + qr;
            *(float2*)&pp[(size_t)r * 192 + n]       = make_float2(d[mi][ni][0], d[mi][ni][1]);
            *(float2*)&pp[(size_t)(r + 8) * 192 + n] = make_float2(d[mi][ni][2], d[mi][ni][3]);
        }
    }
    __threadfence();
    if (tid == 0) islast = atomicAdd(&g_flag[blockIdx.x], 1);
    __syncthreads();
    if (islast == 0) return;
    __threadfence();   // acquire side: other CTA's stores now visible

    // ---- fused reduction epilogue (this CTA is last) ----
    const float* po = g_qkvp + (size_t)(blockIdx.y ^ 1) * MT * 192;
    float* vt = smq;   // 64 x 68 staging for v transpose (pipeline smem free)

    #pragma unroll
    for (int mi = 0; mi < 2; mi++) {
        #pragma unroll
        for (int ni = 0; ni < 6; ni++) {
            int n = wn * 48 + ni * 8 + 2 * qc;
            #pragma unroll
            for (int half = 0; half < 2; half++) {
                int r = m0 + wm * 32 + mi * 16 + qr + half * 8;
                int rl = r - m0;
                float2 o2 = *(const float2*)&po[(size_t)r * 192 + n];
                float v0 = d[mi][ni][2 * half + 0] + o2.x;
                float v1 = d[mi][ni][2 * half + 1] + o2.y;
                if (n < 128) {
                    float sc = (n < 64) ? 0.125f : 1.0f;
                    float* dst = (n < 64) ? g_q : g_k;
                    int base = n & 64 ? (n - 64) : n;   // col within dst
                    int go = (base >> 3) * 8;
                    int c  = base & 7;
                    dst[(size_t)r * HSZ + go + perm8(c)]     = f2tff(v0 * sc);
                    dst[(size_t)r * HSZ + go + perm8(c + 1)] = f2tff(v1 * sc);
                } else {
                    vt[rl * 68 + (n - 128)]     = f2tff(v0);
                    vt[rl * 68 + (n - 128) + 1] = f2tff(v1);
                }
            }
        }
    }
    __syncthreads();

    // transposed + token-permuted write: g_v[batch][hs][tok]
    int batch = m0 >> 11, tokb = m0 & 2047;
    #pragma unroll
    for (int it = 0; it < 4; it++) {
        int gi = it * 256 + tid;
        int h = gi >> 4, u = gi & 15;
        int g8 = (u >> 1) * 8, lo = u & 1;
        int c0 = g8 + (lo ? 2 : 0), c1 = g8 + (lo ? 6 : 4);
        int c2 = g8 + (lo ? 3 : 1), c3 = g8 + (lo ? 7 : 5);
        float4 o = make_float4(vt[c0 * 68 + h], vt[c1 * 68 + h],
                               vt[c2 * 68 + h], vt[c3 * 68 + h]);
        *(float4*)&g_v[(size_t)(batch * 64 + h) * 2048 + tokb + u * 4] = o;
    }
}

// ---------------------------------------------------------------------------
// Flash attention via HMMA tf32, SPLIT-K(4), Bq=64, warp-local softmax.
// (R12 version, unchanged)
// ---------------------------------------------------------------------------
#define ATTN_SMEM 108544
__global__ __launch_bounds__(128, 2) void attn_mma()
{
    extern __shared__ float sma[];
    float* Qs  = sma;                 // 64*68 = 4352
    float* KbS = sma + 4352;          // 2 x 64*72
    float* VbS = sma + 13568;         // 2 x 64*72
    float* Pw  = sma + 22784;         // 4 x 16*68

    const int b = blockIdx.y;
    const int chunk = blockIdx.z;
    const int tid = threadIdx.x, lane = tid & 31, w = tid >> 5;
    const int g = lane >> 2, t = lane & 3;
    const int rr = tid >> 4, cc4 = (tid & 15) * 4;
    const int rA = w * 16 + g, rB = rA + 8;
    float* Pu = Pw + w * 1088;

    const int p0i = 2 * ((2 * t) & 3) + ((2 * t) >> 2);
    const int p1i = 2 * ((2 * t + 1) & 3) + ((2 * t + 1) >> 2);

    const float* qb  = g_q + (size_t)b * TT * HSZ;
    const float* kb  = g_k + (size_t)b * TT * HSZ;
    const float* vtb = g_v + (size_t)b * HSZ * TT;
    float* po = g_po + (size_t)chunk * MT * HSZ + (size_t)b * TT * HSZ;
    float* pm = g_pm + (size_t)chunk * MT + (size_t)b * TT;
    float* pl = g_pl + (size_t)chunk * MT + (size_t)b * TT;

    const uint32_t sQ = smem_u32(Qs), sK = smem_u32(KbS), sV = smem_u32(VbS);

    for (int half = 0; half < 2; half++) {
        const int qt   = half ? (31 - (int)blockIdx.x) : (int)blockIdx.x;
        const int row0 = qt * 64;
        const int nkt  = qt + 1;
        const int jb   = (chunk * nkt) >> 2;
        const int je   = ((chunk + 1) * nkt) >> 2;

        if (jb == je) {
            if (tid < 64) { pm[row0 + tid] = -INFINITY; pl[row0 + tid] = 0.f; }
            continue;
        }

        __syncthreads();
        #pragma unroll
        for (int p = 0; p < 8; p++) {
            int r = p * 8 + rr;
            CP16(sQ + (uint32_t)(r * 68 + cc4) * 4, &qb[(size_t)(row0 + r) * HSZ + cc4]);
        }
        {
            int t0 = jb * 64;
            #pragma unroll
            for (int p = 0; p < 8; p++) {
                int r = p * 8 + rr;
                CP16(sK + (uint32_t)(r * 72 + cc4) * 4, &kb[(size_t)(t0 + r) * HSZ + cc4]);
                CP16(sV + (uint32_t)(r * 72 + cc4) * 4, &vtb[(size_t)r * 2048 + t0 + cc4]);
            }
        }
        CP_COMMIT();
        CP_WAIT0();
        __syncthreads();

        uint32_t qf[8][4];
        #pragma unroll
        for (int kk = 0; kk < 8; kk++) {
            uint2 u0 = *(const uint2*)&Qs[rA * 68 + kk * 8 + 2 * t];
            uint2 u1 = *(const uint2*)&Qs[rB * 68 + kk * 8 + 2 * t];
            qf[kk][0] = u0.x; qf[kk][2] = u0.y;
            qf[kk][1] = u1.x; qf[kk][3] = u1.y;
        }

        float oa[8][4] = {};
        float rm0 = -INFINITY, rm1 = -INFINITY, rl0 = 0.f, rl1 = 0.f;

        for (int j = jb; j < je; j++) {
            const int bsel = (j - jb) & 1;
            const float* Ks = KbS + bsel * 4608;
            const float* Vs = VbS + bsel * 4608;
            if (j > jb) { CP_WAIT0(); __syncthreads(); }

            if (j + 1 < je) {
                int t0n = (j + 1) * 64;
                uint32_t dK = sK + (uint32_t)((bsel ^ 1) * 4608) * 4;
                uint32_t dV = sV + (uint32_t)((bsel ^ 1) * 4608) * 4;
                #pragma unroll
                for (int p = 0; p < 8; p++) {
                    int r = p * 8 + rr;
                    CP16(dK + (uint32_t)(r * 72 + cc4) * 4, &kb[(size_t)(t0n + r) * HSZ + cc4]);
                    CP16(dV + (uint32_t)(r * 72 + cc4) * 4, &vtb[(size_t)r * 2048 + t0n + cc4]);
                }
                CP_COMMIT();
            }

            float sa[8][4] = {};
            #pragma unroll
            for (int kk = 0; kk < 8; kk++) {
                #pragma unroll
                for (int f = 0; f < 8; f++) {
                    uint2 bv = *(const uint2*)&Ks[(f * 8 + g) * 72 + kk * 8 + 2 * t];
                    mma1688(sa[f], qf[kk][0], qf[kk][1], qf[kk][2], qf[kk][3], bv.x, bv.y);
                }
            }

            const bool diag = (j == nkt - 1);
            const int t0 = j * 64;
            if (diag) {
                #pragma unroll
                for (int f = 0; f < 8; f++) {
                    int col = t0 + f * 8 + 2 * t;
                    int gA = row0 + rA, gB = row0 + rB;
                    if (col     > gA) sa[f][0] = -INFINITY;
                    if (col + 1 > gA) sa[f][1] = -INFINITY;
                    if (col     > gB) sa[f][2] = -INFINITY;
                    if (col + 1 > gB) sa[f][3] = -INFINITY;
                }
            }
            float pm0 = fmaxf(sa[0][0], sa[0][1]), pm1 = fmaxf(sa[0][2], sa[0][3]);
            #pragma unroll
            for (int f = 1; f < 8; f++) {
                pm0 = fmaxf(pm0, fmaxf(sa[f][0], sa[f][1]));
                pm1 = fmaxf(pm1, fmaxf(sa[f][2], sa[f][3]));
            }
            pm0 = fmaxf(pm0, __shfl_xor_sync(0xffffffffu, pm0, 1));
            pm0 = fmaxf(pm0, __shfl_xor_sync(0xffffffffu, pm0, 2));
            pm1 = fmaxf(pm1, __shfl_xor_sync(0xffffffffu, pm1, 1));
            pm1 = fmaxf(pm1, __shfl_xor_sync(0xffffffffu, pm1, 2));
            float mn0 = fmaxf(rm0, pm0), mn1 = fmaxf(rm1, pm1);
            float al0 = __expf(rm0 - mn0), al1 = __expf(rm1 - mn1);

            float ps0 = 0.f, ps1 = 0.f;
            #pragma unroll
            for (int f = 0; f < 8; f++) {
                float e0 = __expf(sa[f][0] - mn0), e1 = __expf(sa[f][1] - mn0);
                float e2 = __expf(sa[f][2] - mn1), e3 = __expf(sa[f][3] - mn1);
                ps0 += e0 + e1; ps1 += e2 + e3;
                Pu[g * 68 + f * 8 + p0i]       = f2tff(e0);
                Pu[g * 68 + f * 8 + p1i]       = f2tff(e1);
                Pu[(g + 8) * 68 + f * 8 + p0i] = f2tff(e2);
                Pu[(g + 8) * 68 + f * 8 + p1i] = f2tff(e3);
            }
            ps0 += __shfl_xor_sync(0xffffffffu, ps0, 1);
            ps0 += __shfl_xor_sync(0xffffffffu, ps0, 2);
            ps1 += __shfl_xor_sync(0xffffffffu, ps1, 1);
            ps1 += __shfl_xor_sync(0xffffffffu, ps1, 2);
            rl0 = rl0 * al0 + ps0;
            rl1 = rl1 * al1 + ps1;
            rm0 = mn0; rm1 = mn1;
            #pragma unroll
            for (int f = 0; f < 8; f++) {
                oa[f][0] *= al0; oa[f][1] *= al0;
                oa[f][2] *= al1; oa[f][3] *= al1;
            }
            __syncwarp();

            #pragma unroll
            for (int kk = 0; kk < 8; kk++) {
                uint2 a02 = *(const uint2*)&Pu[g * 68 + kk * 8 + 2 * t];
                uint2 a13 = *(const uint2*)&Pu[(g + 8) * 68 + kk * 8 + 2 * t];
                #pragma unroll
                for (int f = 0; f < 8; f++) {
                    uint2 bv = *(const uint2*)&Vs[(f * 8 + g) * 72 + kk * 8 + 2 * t];
                    mma1688(oa[f], a02.x, a13.x, a02.y, a13.y, bv.x, bv.y);
                }
            }
        }

        #pragma unroll
        for (int f = 0; f < 8; f++) {
            int col = f * 8 + 2 * t;
            *(float2*)&po[(size_t)(row0 + rA) * HSZ + col] = make_float2(oa[f][0], oa[f][1]);
            *(float2*)&po[(size_t)(row0 + rB) * HSZ + col] = make_float2(oa[f][2], oa[f][3]);
        }
        if (t == 0) {
            pm[row0 + rA] = rm0; pm[row0 + rB] = rm1;
            pl[row0 + rA] = rl0; pl[row0 + rB] = rl1;
        }
    }
}

// ---------------------------------------------------------------------------
// out_mm, fused 4-way merge, double-buffered B tiles (R12 version).
// ---------------------------------------------------------------------------
#define OSTG (128 * OSTR)
#define OUT_SMEM ((64*OSTR + 256 + 2*OSTG) * 4)
__global__ __launch_bounds__(256) void out_mm(const float* __restrict__ bp,
                                              float* __restrict__ out)
{
    extern __shared__ float smo[];
    float* As  = smo;                       // 64 x OSTR
    float* sc  = smo + 64 * OSTR;           // 64 x 4
    float* Bs0 = smo + 64 * OSTR + 256;     // stage 0
    float* Bs1 = Bs0 + OSTG;                // stage 1

    const int tid = threadIdx.x, lane = tid & 31, wid = tid >> 5;
    const int qr = lane >> 2, qc = lane & 3;
    const int wm = wid & 1, wn = wid >> 1;
    const int m0 = blockIdx.x * 64;

    if (tid < 64) {
        int row = m0 + tid;
        float m0v = g_pm[row], m1v = g_pm[MT + row], m2v = g_pm[2*MT + row], m3v = g_pm[3*MT + row];
        float mm = fmaxf(fmaxf(m0v, m1v), fmaxf(m2v, m3v));
        float e0 = __expf(m0v - mm), e1 = __expf(m1v - mm);
        float e2 = __expf(m2v - mm), e3 = __expf(m3v - mm);
        float il = 1.f / (g_pl[row] * e0 + g_pl[MT + row] * e1 +
                          g_pl[2*MT + row] * e2 + g_pl[3*MT + row] * e3);
        sc[tid * 4 + 0] = e0 * il; sc[tid * 4 + 1] = e1 * il;
        sc[tid * 4 + 2] = e2 * il; sc[tid * 4 + 3] = e3 * il;
    }
    __syncthreads();

    #pragma unroll
    for (int it = 0; it < 4; it++) {
        int gi = it * 256 + tid;
        int r = gi >> 4, q = gi & 15;
        size_t base = (size_t)(m0 + r) * HSZ + q * 4;
        float w0 = sc[r * 4 + 0], w1 = sc[r * 4 + 1], w2 = sc[r * 4 + 2], w3 = sc[r * 4 + 3];
        float4 a = *(const float4*)&g_po[base];
        float4 b = *(const float4*)&g_po[(size_t)MT * HSZ + base];
        float4 c = *(const float4*)&g_po[(size_t)2 * MT * HSZ + base];
        float4 d4 = *(const float4*)&g_po[(size_t)3 * MT * HSZ + base];
        float v0 = a.x*w0 + b.x*w1 + c.x*w2 + d4.x*w3;
        float v1 = a.y*w0 + b.y*w1 + c.y*w2 + d4.y*w3;
        float v2 = a.z*w0 + b.z*w1 + c.z*w2 + d4.z*w3;
        float v3 = a.w*w0 + b.w*w1 + c.w*w2 + d4.w*w3;
        uint32_t* s = (uint32_t*)&As[r * OSTR + (q >> 1) * 8 + (q & 1)];
        s[0] = f2tf(v0); s[2] = f2tf(v1); s[4] = f2tf(v2); s[6] = f2tf(v3);
    }

    float4 bR[8];
    #pragma unroll
    for (int i = 0; i < 8; i++) {
        int id = i * 256 + tid, r = id >> 4, q = id & 15;
        bR[i] = *(const float4*)&g_wpsumT[(size_t)r * HSZ + q * 4];
    }
    __syncthreads();

    uint32_t af[2][8][4];
    #pragma unroll
    for (int kk = 0; kk < 8; kk++) {
        #pragma unroll
        for (int mi = 0; mi < 2; mi++) {
            uint2 lo = *(const uint2*)&As[(wm * 32 + mi * 16 + qr) * OSTR + kk * 8 + 2 * qc];
            uint2 hi = *(const uint2*)&As[(wm * 32 + mi * 16 + qr + 8) * OSTR + kk * 8 + 2 * qc];
            af[mi][kk][0] = lo.x; af[mi][kk][1] = hi.x;
            af[mi][kk][2] = lo.y; af[mi][kk][3] = hi.y;
        }
    }

    #pragma unroll
    for (int i = 0; i < 8; i++) {
        int id = i * 256 + tid, r = id >> 4, q = id & 15;
        uint32_t* s = (uint32_t*)&Bs0[r * OSTR + (q >> 1) * 8 + (q & 1)];
        s[0] = f2tf(bR[i].x); s[2] = f2tf(bR[i].y);
        s[4] = f2tf(bR[i].z); s[6] = f2tf(bR[i].w);
    }
    #pragma unroll
    for (int i = 0; i < 8; i++) {
        int id = i * 256 + tid, r = id >> 4, q = id & 15;
        bR[i] = *(const float4*)&g_wpsumT[(size_t)(128 + r) * HSZ + q * 4];
    }
    __syncthreads();

    for (int nt = 0; nt < 8; nt++) {
        const int n0 = nt * 128;
        float* S = (nt & 1) ? Bs1 : Bs0;

        if (nt < 7) {
            float* D = (nt & 1) ? Bs0 : Bs1;
            #pragma unroll
            for (int i = 0; i < 8; i++) {
                int id = i * 256 + tid, r = id >> 4, q = id & 15;
                uint32_t* s = (uint32_t*)&D[r * OSTR + (q >> 1) * 8 + (q & 1)];
                s[0] = f2tf(bR[i].x); s[2] = f2tf(bR[i].y);
                s[4] = f2tf(bR[i].z); s[6] = f2tf(bR[i].w);
            }
            if (nt < 6) {
                #pragma unroll
                for (int i = 0; i < 8; i++) {
                    int id = i * 256 + tid, r = id >> 4, q = id & 15;
                    bR[i] = *(const float4*)&g_wpsumT[(size_t)(n0 + 256 + r) * HSZ + q * 4];
                }
            }
        }

        float d[2][4][4] = {};
        #pragma unroll
        for (int kk = 0; kk < 8; kk++) {
            #pragma unroll
            for (int ni = 0; ni < 4; ni++) {
                uint2 bf = *(const uint2*)&S[(wn * 32 + ni * 8 + qr) * OSTR + kk * 8 + 2 * qc];
                mma1688(d[0][ni], af[0][kk][0], af[0][kk][1], af[0][kk][2], af[0][kk][3], bf.x, bf.y);
                mma1688(d[1][ni], af[1][kk][0], af[1][kk][1], af[1][kk][2], af[1][kk][3], bf.x, bf.y);
            }
        }

        #pragma unroll
        for (int mi = 0; mi < 2; mi++) {
            #pragma unroll
            for (int ni = 0; ni < 4; ni++) {
                int n = n0 + wn * 32 + ni * 8 + 2 * qc;
                float2 b2 = *(const float2*)&bp[n];
                int r = m0 + wm * 32 + mi * 16 + qr;
                *(float2*)&out[(size_t)r * EE + n] =
                    make_float2(d[mi][ni][0] + b2.x, d[mi][ni][1] + b2.y);
                *(float2*)&out[(size_t)(r + 8) * EE + n] =
                    make_float2(d[mi][ni][2] + b2.x, d[mi][ni][3] + b2.y);
            }
        }
        __syncthreads();
    }
}

// ---------------------------------------------------------------------------
extern "C" void kernel_launch(void* const* d_in, const int* in_sizes, int n_in,
                              void* d_out, int out_size)
{
    const float* x  = (const float*)d_in[0];
    const float* Wq = (const float*)d_in[1];
    const float* Wk = (const float*)d_in[2];
    const float* Wv = (const float*)d_in[3];
    const float* Wp = (const float*)d_in[4];
    const float* bp = (const float*)d_in[5];
    float* out = (float*)d_out;

    cudaFuncSetAttribute(attn_mma, cudaFuncAttributeMaxDynamicSharedMemorySize, ATTN_SMEM);
    cudaFuncSetAttribute(qkv_mm,   cudaFuncAttributeMaxDynamicSharedMemorySize, QKV_SMEM);
    cudaFuncSetAttribute(out_mm,   cudaFuncAttributeMaxDynamicSharedMemorySize, OUT_SMEM);

    prep_kernel<<<832, 256>>>(Wq, Wk, Wv, Wp);
    qkv_mm<<<dim3(128, 2), 256, QKV_SMEM>>>(x);
    attn_mma<<<dim3(16, BB, 4), 128, ATTN_SMEM>>>();
    out_mm<<<128, 256, OUT_SMEM>>>(bp, out);
}

// round 14
// speedup vs baseline: 1.0110x; 1.0110x over previous
#include <cuda_runtime.h>
#include <math.h>
#include <stdint.h>

#define BB 4
#define TT 2048
#define EE 1024
#define HSZ 64
#define NHEAD 16
#define MT (BB*TT)

// Scratch (allocation-free rule: device globals)
// g_q: [MT][64] tf32, hs-cols fragment-permuted, PRE-SCALED by 0.125 (exact pow2)
// g_k: [MT][64] tf32, hs-cols fragment-permuted
// g_v: [BB][64][2048] = v^T per batch, token-cols fragment-permuted, tf32
__device__ float g_q[MT*HSZ];
__device__ float g_k[MT*HSZ];
__device__ float g_v[MT*HSZ];
__device__ float g_wt[192*EE];        // packed [n][k]: Wq^T | Wk^T | Wv^T
__device__ float g_wpsumT[EE*HSZ];    // [f][h] = sum_n Wp[n*64+h][f]
__device__ float g_qkvp[2*MT*192];    // qkv split-K(2) partials
__device__ float g_po[4*MT*HSZ];      // attn split-k partial O (unnormalized)
__device__ float g_pm[4*MT];          // attn partial row max
__device__ float g_pl[4*MT];          // attn partial row sum

// ---------------- HMMA helpers (baseline PTX, no 'a'-suffix features) -------
__device__ __forceinline__ uint32_t f2tf(float f) {
    uint32_t r; asm("cvt.rna.tf32.f32 %0, %1;" : "=r"(r) : "f"(f)); return r;
}
__device__ __forceinline__ float f2tff(float f) { return __uint_as_float(f2tf(f)); }
__device__ __forceinline__ void mma1688(float d[4], uint32_t a0, uint32_t a1,
                                        uint32_t a2, uint32_t a3,
                                        uint32_t b0, uint32_t b1) {
    asm volatile(
        "mma.sync.aligned.m16n8k8.row.col.f32.tf32.tf32.f32 "
        "{%0,%1,%2,%3},{%4,%5,%6,%7},{%8,%9},{%0,%1,%2,%3};"
        : "+f"(d[0]), "+f"(d[1]), "+f"(d[2]), "+f"(d[3])
        : "r"(a0), "r"(a1), "r"(a2), "r"(a3), "r"(b0), "r"(b1));
}
__device__ __forceinline__ uint32_t smem_u32(const void* p) {
    uint32_t a;
    asm("{ .reg .u64 t; cvta.to.shared.u64 t, %1; cvt.u32.u64 %0, t; }" : "=r"(a) : "l"(p));
    return a;
}
#define CP16(dst, src) asm volatile("cp.async.cg.shared.global [%0], [%1], 16;" :: "r"(dst), "l"(src) : "memory")
#define CP_COMMIT()    asm volatile("cp.async.commit_group;" ::: "memory")
#define CP_WAIT0()     asm volatile("cp.async.wait_group 0;" ::: "memory")

#define ASTR 36   // GEMM smem row stride for K=32 tiles
#define OSTR 68   // out_mm smem row stride for K=64 tiles

// ---------------------------------------------------------------------------
// prep (fused): blocks 0..767 pack W^T; 768..831 wpsumT (coalesced).  (R12)
// ---------------------------------------------------------------------------
__global__ __launch_bounds__(256) void prep_kernel(const float* __restrict__ Wq,
                                                   const float* __restrict__ Wk,
                                                   const float* __restrict__ Wv,
                                                   const float* __restrict__ Wp)
{
    __shared__ float st[64 * 20];
    int bx = blockIdx.x, tid = threadIdx.x;
    if (bx < 768) {
        int idx = bx * 256 + tid;
        int n = idx >> 10, k = idx & 1023;
        float v = (n < 64) ? Wq[k * 64 + n] : (n < 128) ? Wk[k * 64 + (n - 64)] : Wv[k * 64 + (n - 128)];
        g_wt[idx] = v;
        return;
    }
    const int f0 = (bx - 768) * 16;
    {
        int sub = tid >> 6, h = tid & 63;
        float4 s = make_float4(0.f, 0.f, 0.f, 0.f);
        #pragma unroll
        for (int n = 0; n < 16; n++) {
            float4 v = *(const float4*)&Wp[(size_t)(n * 64 + h) * EE + f0 + sub * 4];
            s.x += v.x; s.y += v.y; s.z += v.z; s.w += v.w;
        }
        *(float4*)&st[h * 20 + sub * 4] = s;
    }
    __syncthreads();
    {
        int fl = tid >> 4, h4 = (tid & 15) * 4;
        float4 o = make_float4(st[(h4 + 0) * 20 + fl], st[(h4 + 1) * 20 + fl],
                               st[(h4 + 2) * 20 + fl], st[(h4 + 3) * 20 + fl]);
        *(float4*)&g_wpsumT[(size_t)(f0 + fl) * HSZ + h4] = o;
    }
}

// ---------------------------------------------------------------------------
// qkv via HMMA tf32, SPLIT-K(2), 2-stage smem pipeline.  (R12, proven)
// ---------------------------------------------------------------------------
#define QSTG 9216
#define QKV_SMEM (2 * QSTG * 4)
__global__ __launch_bounds__(256) void qkv_mm(const float* __restrict__ x)
{
    extern __shared__ float smq[];

    const int tid = threadIdx.x, lane = tid & 31, wid = tid >> 5;
    const int qr = lane >> 2, qc = lane & 3;
    const int wm = wid & 1, wn = wid >> 1;
    const int m0 = blockIdx.x * 64;
    const int kbase = blockIdx.y * 512;

    const int fr2 = tid >> 3, fkq = tid & 7;

    float4 aR[2], bR[6];

    #pragma unroll
    for (int i = 0; i < 2; i++) {
        int r = i * 32 + fr2;
        aR[i] = *(const float4*)&x[(size_t)(m0 + r) * EE + kbase + fkq * 4];
    }
    #pragma unroll
    for (int i = 0; i < 6; i++) {
        int r = i * 32 + fr2;
        bR[i] = *(const float4*)&g_wt[(size_t)r * EE + kbase + fkq * 4];
    }
    {
        float* D = smq;
        #pragma unroll
        for (int i = 0; i < 2; i++) {
            int r = i * 32 + fr2;
            uint32_t* s = (uint32_t*)&D[r * ASTR + (fkq >> 1) * 8 + (fkq & 1)];
            s[0] = f2tf(aR[i].x); s[2] = f2tf(aR[i].y);
            s[4] = f2tf(aR[i].z); s[6] = f2tf(aR[i].w);
        }
        #pragma unroll
        for (int i = 0; i < 6; i++) {
            int r = i * 32 + fr2;
            uint32_t* s = (uint32_t*)&D[2304 + r * ASTR + (fkq >> 1) * 8 + (fkq & 1)];
            s[0] = f2tf(bR[i].x); s[2] = f2tf(bR[i].y);
            s[4] = f2tf(bR[i].z); s[6] = f2tf(bR[i].w);
        }
    }
    #pragma unroll
    for (int i = 0; i < 2; i++) {
        int r = i * 32 + fr2;
        aR[i] = *(const float4*)&x[(size_t)(m0 + r) * EE + kbase + 32 + fkq * 4];
    }
    #pragma unroll
    for (int i = 0; i < 6; i++) {
        int r = i * 32 + fr2;
        bR[i] = *(const float4*)&g_wt[(size_t)r * EE + kbase + 32 + fkq * 4];
    }
    __syncthreads();

    float d[2][6][4] = {};

    for (int kt = 0; kt < 16; kt++) {
        float* S = smq + (kt & 1) * QSTG;

        if (kt < 15) {
            float* D = smq + ((kt & 1) ^ 1) * QSTG;
            #pragma unroll
            for (int i = 0; i < 2; i++) {
                int r = i * 32 + fr2;
                uint32_t* s = (uint32_t*)&D[r * ASTR + (fkq >> 1) * 8 + (fkq & 1)];
                s[0] = f2tf(aR[i].x); s[2] = f2tf(aR[i].y);
                s[4] = f2tf(aR[i].z); s[6] = f2tf(aR[i].w);
            }
            #pragma unroll
            for (int i = 0; i < 6; i++) {
                int r = i * 32 + fr2;
                uint32_t* s = (uint32_t*)&D[2304 + r * ASTR + (fkq >> 1) * 8 + (fkq & 1)];
                s[0] = f2tf(bR[i].x); s[2] = f2tf(bR[i].y);
                s[4] = f2tf(bR[i].z); s[6] = f2tf(bR[i].w);
            }
            if (kt < 14) {
                int k0 = kbase + (kt + 2) * 32;
                #pragma unroll
                for (int i = 0; i < 2; i++) {
                    int r = i * 32 + fr2;
                    aR[i] = *(const float4*)&x[(size_t)(m0 + r) * EE + k0 + fkq * 4];
                }
                #pragma unroll
                for (int i = 0; i < 6; i++) {
                    int r = i * 32 + fr2;
                    bR[i] = *(const float4*)&g_wt[(size_t)r * EE + k0 + fkq * 4];
                }
            }
        }

        #pragma unroll
        for (int g = 0; g < 4; g++) {
            uint32_t af[2][4];
            #pragma unroll
            for (int mi = 0; mi < 2; mi++) {
                uint2 lo = *(const uint2*)&S[(wm * 32 + mi * 16 + qr) * ASTR + g * 8 + 2 * qc];
                uint2 hi = *(const uint2*)&S[(wm * 32 + mi * 16 + qr + 8) * ASTR + g * 8 + 2 * qc];
                af[mi][0] = lo.x; af[mi][1] = hi.x; af[mi][2] = lo.y; af[mi][3] = hi.y;
            }
            #pragma unroll
            for (int ni = 0; ni < 6; ni++) {
                uint2 bf = *(const uint2*)&S[2304 + (wn * 48 + ni * 8 + qr) * ASTR + g * 8 + 2 * qc];
                mma1688(d[0][ni], af[0][0], af[0][1], af[0][2], af[0][3], bf.x, bf.y);
                mma1688(d[1][ni], af[1][0], af[1][1], af[1][2], af[1][3], bf.x, bf.y);
            }
        }
        __syncthreads();
    }

    float* pp = g_qkvp + (size_t)blockIdx.y * MT * 192;
    #pragma unroll
    for (int mi = 0; mi < 2; mi++) {
        #pragma unroll
        for (int ni = 0; ni < 6; ni++) {
            int n = wn * 48 + ni * 8 + 2 * qc;
            int r = m0 + wm * 32 + mi * 16 + qr;
            *(float2*)&pp[(size_t)r * 192 + n]       = make_float2(d[mi][ni][0], d[mi][ni][1]);
            *(float2*)&pp[(size_t)(r + 8) * 192 + n] = make_float2(d[mi][ni][2], d[mi][ni][3]);
        }
    }
}

// ---------------------------------------------------------------------------
// qkv_add: sum 2 split-K partials, tf32 round, fragment permutes, q pre-scale.
// (R12, proven)
// ---------------------------------------------------------------------------
__global__ __launch_bounds__(256) void qkv_add()
{
    __shared__ float vt[64 * 68];
    const int tid = threadIdx.x;
    const int m0 = blockIdx.x * 64;
    const float* p0 = g_qkvp;
    const float* p1 = g_qkvp + (size_t)MT * 192;

    #pragma unroll
    for (int it = 0; it < 4; it++) {
        int gi = it * 256 + tid;
        int r = gi >> 4, grp = gi & 15;
        size_t base = (size_t)(m0 + r) * 192 + grp * 8;
        float sc = (grp < 8) ? 0.125f : 1.0f;
        float4 a0 = *(const float4*)&p0[base],     a1 = *(const float4*)&p0[base + 4];
        float4 b0 = *(const float4*)&p1[base],     b1 = *(const float4*)&p1[base + 4];
        float s0 = f2tff((a0.x + b0.x) * sc), s1 = f2tff((a0.y + b0.y) * sc);
        float s2 = f2tff((a0.z + b0.z) * sc), s3 = f2tff((a0.w + b0.w) * sc);
        float s4 = f2tff((a1.x + b1.x) * sc), s5 = f2tff((a1.y + b1.y) * sc);
        float s6 = f2tff((a1.z + b1.z) * sc), s7 = f2tff((a1.w + b1.w) * sc);
        float* dst = (grp < 8) ? g_q : g_k;
        int col = (grp & 7) * 8;
        *(float4*)&dst[(size_t)(m0 + r) * HSZ + col]     = make_float4(s0, s4, s1, s5);
        *(float4*)&dst[(size_t)(m0 + r) * HSZ + col + 4] = make_float4(s2, s6, s3, s7);
    }

    #pragma unroll
    for (int it = 0; it < 4; it++) {
        int gi = it * 256 + tid;
        int r = gi >> 4, c4 = (gi & 15) * 4;
        size_t base = (size_t)(m0 + r) * 192 + 128 + c4;
        float4 a = *(const float4*)&p0[base];
        float4 b = *(const float4*)&p1[base];
        *(float4*)&vt[r * 68 + c4] = make_float4(f2tff(a.x + b.x), f2tff(a.y + b.y),
                                                 f2tff(a.z + b.z), f2tff(a.w + b.w));
    }
    __syncthreads();

    int batch = m0 >> 11, tokb = m0 & 2047;
    #pragma unroll
    for (int it = 0; it < 4; it++) {
        int gi = it * 256 + tid;
        int h = gi >> 4, u = gi & 15;
        int g8 = (u >> 1) * 8, lo = u & 1;
        int c0 = g8 + (lo ? 2 : 0), c1 = g8 + (lo ? 6 : 4);
        int c2 = g8 + (lo ? 3 : 1), c3 = g8 + (lo ? 7 : 5);
        float4 o = make_float4(vt[c0 * 68 + h], vt[c1 * 68 + h],
                               vt[c2 * 68 + h], vt[c3 * 68 + h]);
        *(float4*)&g_v[(size_t)(batch * 64 + h) * 2048 + tokb + u * 4] = o;
    }
}

// ---------------------------------------------------------------------------
// Flash attention via HMMA tf32, SPLIT-K(4), Bq=64, warp-local softmax.
// (R12, proven at 28.2us)
// ---------------------------------------------------------------------------
#define ATTN_SMEM 108544
__global__ __launch_bounds__(128, 2) void attn_mma()
{
    extern __shared__ float sma[];
    float* Qs  = sma;
    float* KbS = sma + 4352;
    float* VbS = sma + 13568;
    float* Pw  = sma + 22784;

    const int b = blockIdx.y;
    const int chunk = blockIdx.z;
    const int tid = threadIdx.x, lane = tid & 31, w = tid >> 5;
    const int g = lane >> 2, t = lane & 3;
    const int rr = tid >> 4, cc4 = (tid & 15) * 4;
    const int rA = w * 16 + g, rB = rA + 8;
    float* Pu = Pw + w * 1088;

    const int p0i = 2 * ((2 * t) & 3) + ((2 * t) >> 2);
    const int p1i = 2 * ((2 * t + 1) & 3) + ((2 * t + 1) >> 2);

    const float* qb  = g_q + (size_t)b * TT * HSZ;
    const float* kb  = g_k + (size_t)b * TT * HSZ;
    const float* vtb = g_v + (size_t)b * HSZ * TT;
    float* po = g_po + (size_t)chunk * MT * HSZ + (size_t)b * TT * HSZ;
    float* pm = g_pm + (size_t)chunk * MT + (size_t)b * TT;
    float* pl = g_pl + (size_t)chunk * MT + (size_t)b * TT;

    const uint32_t sQ = smem_u32(Qs), sK = smem_u32(KbS), sV = smem_u32(VbS);

    for (int half = 0; half < 2; half++) {
        const int qt   = half ? (31 - (int)blockIdx.x) : (int)blockIdx.x;
        const int row0 = qt * 64;
        const int nkt  = qt + 1;
        const int jb   = (chunk * nkt) >> 2;
        const int je   = ((chunk + 1) * nkt) >> 2;

        if (jb == je) {
            if (tid < 64) { pm[row0 + tid] = -INFINITY; pl[row0 + tid] = 0.f; }
            continue;
        }

        __syncthreads();
        #pragma unroll
        for (int p = 0; p < 8; p++) {
            int r = p * 8 + rr;
            CP16(sQ + (uint32_t)(r * 68 + cc4) * 4, &qb[(size_t)(row0 + r) * HSZ + cc4]);
        }
        {
            int t0 = jb * 64;
            #pragma unroll
            for (int p = 0; p < 8; p++) {
                int r = p * 8 + rr;
                CP16(sK + (uint32_t)(r * 72 + cc4) * 4, &kb[(size_t)(t0 + r) * HSZ + cc4]);
                CP16(sV + (uint32_t)(r * 72 + cc4) * 4, &vtb[(size_t)r * 2048 + t0 + cc4]);
            }
        }
        CP_COMMIT();
        CP_WAIT0();
        __syncthreads();

        uint32_t qf[8][4];
        #pragma unroll
        for (int kk = 0; kk < 8; kk++) {
            uint2 u0 = *(const uint2*)&Qs[rA * 68 + kk * 8 + 2 * t];
            uint2 u1 = *(const uint2*)&Qs[rB * 68 + kk * 8 + 2 * t];
            qf[kk][0] = u0.x; qf[kk][2] = u0.y;
            qf[kk][1] = u1.x; qf[kk][3] = u1.y;
        }

        float oa[8][4] = {};
        float rm0 = -INFINITY, rm1 = -INFINITY, rl0 = 0.f, rl1 = 0.f;

        for (int j = jb; j < je; j++) {
            const int bsel = (j - jb) & 1;
            const float* Ks = KbS + bsel * 4608;
            const float* Vs = VbS + bsel * 4608;
            if (j > jb) { CP_WAIT0(); __syncthreads(); }

            if (j + 1 < je) {
                int t0n = (j + 1) * 64;
                uint32_t dK = sK + (uint32_t)((bsel ^ 1) * 4608) * 4;
                uint32_t dV = sV + (uint32_t)((bsel ^ 1) * 4608) * 4;
                #pragma unroll
                for (int p = 0; p < 8; p++) {
                    int r = p * 8 + rr;
                    CP16(dK + (uint32_t)(r * 72 + cc4) * 4, &kb[(size_t)(t0n + r) * HSZ + cc4]);
                    CP16(dV + (uint32_t)(r * 72 + cc4) * 4, &vtb[(size_t)r * 2048 + t0n + cc4]);
                }
                CP_COMMIT();
            }

            float sa[8][4] = {};
            #pragma unroll
            for (int kk = 0; kk < 8; kk++) {
                #pragma unroll
                for (int f = 0; f < 8; f++) {
                    uint2 bv = *(const uint2*)&Ks[(f * 8 + g) * 72 + kk * 8 + 2 * t];
                    mma1688(sa[f], qf[kk][0], qf[kk][1], qf[kk][2], qf[kk][3], bv.x, bv.y);
                }
            }

            const bool diag = (j == nkt - 1);
            const int t0 = j * 64;
            if (diag) {
                #pragma unroll
                for (int f = 0; f < 8; f++) {
                    int col = t0 + f * 8 + 2 * t;
                    int gA = row0 + rA, gB = row0 + rB;
                    if (col     > gA) sa[f][0] = -INFINITY;
                    if (col + 1 > gA) sa[f][1] = -INFINITY;
                    if (col     > gB) sa[f][2] = -INFINITY;
                    if (col + 1 > gB) sa[f][3] = -INFINITY;
                }
            }
            float pm0 = fmaxf(sa[0][0], sa[0][1]), pm1 = fmaxf(sa[0][2], sa[0][3]);
            #pragma unroll
            for (int f = 1; f < 8; f++) {
                pm0 = fmaxf(pm0, fmaxf(sa[f][0], sa[f][1]));
                pm1 = fmaxf(pm1, fmaxf(sa[f][2], sa[f][3]));
            }
            pm0 = fmaxf(pm0, __shfl_xor_sync(0xffffffffu, pm0, 1));
            pm0 = fmaxf(pm0, __shfl_xor_sync(0xffffffffu, pm0, 2));
            pm1 = fmaxf(pm1, __shfl_xor_sync(0xffffffffu, pm1, 1));
            pm1 = fmaxf(pm1, __shfl_xor_sync(0xffffffffu, pm1, 2));
            float mn0 = fmaxf(rm0, pm0), mn1 = fmaxf(rm1, pm1);
            float al0 = __expf(rm0 - mn0), al1 = __expf(rm1 - mn1);

            float ps0 = 0.f, ps1 = 0.f;
            #pragma unroll
            for (int f = 0; f < 8; f++) {
                float e0 = __expf(sa[f][0] - mn0), e1 = __expf(sa[f][1] - mn0);
                float e2 = __expf(sa[f][2] - mn1), e3 = __expf(sa[f][3] - mn1);
                ps0 += e0 + e1; ps1 += e2 + e3;
                Pu[g * 68 + f * 8 + p0i]       = f2tff(e0);
                Pu[g * 68 + f * 8 + p1i]       = f2tff(e1);
                Pu[(g + 8) * 68 + f * 8 + p0i] = f2tff(e2);
                Pu[(g + 8) * 68 + f * 8 + p1i] = f2tff(e3);
            }
            ps0 += __shfl_xor_sync(0xffffffffu, ps0, 1);
            ps0 += __shfl_xor_sync(0xffffffffu, ps0, 2);
            ps1 += __shfl_xor_sync(0xffffffffu, ps1, 1);
            ps1 += __shfl_xor_sync(0xffffffffu, ps1, 2);
            rl0 = rl0 * al0 + ps0;
            rl1 = rl1 * al1 + ps1;
            rm0 = mn0; rm1 = mn1;
            #pragma unroll
            for (int f = 0; f < 8; f++) {
                oa[f][0] *= al0; oa[f][1] *= al0;
                oa[f][2] *= al1; oa[f][3] *= al1;
            }
            __syncwarp();

            #pragma unroll
            for (int kk = 0; kk < 8; kk++) {
                uint2 a02 = *(const uint2*)&Pu[g * 68 + kk * 8 + 2 * t];
                uint2 a13 = *(const uint2*)&Pu[(g + 8) * 68 + kk * 8 + 2 * t];
                #pragma unroll
                for (int f = 0; f < 8; f++) {
                    uint2 bv = *(const uint2*)&Vs[(f * 8 + g) * 72 + kk * 8 + 2 * t];
                    mma1688(oa[f], a02.x, a13.x, a02.y, a13.y, bv.x, bv.y);
                }
            }
        }

        #pragma unroll
        for (int f = 0; f < 8; f++) {
            int col = f * 8 + 2 * t;
            *(float2*)&po[(size_t)(row0 + rA) * HSZ + col] = make_float2(oa[f][0], oa[f][1]);
            *(float2*)&po[(size_t)(row0 + rB) * HSZ + col] = make_float2(oa[f][2], oa[f][3]);
        }
        if (t == 0) {
            pm[row0 + rA] = rm0; pm[row0 + rB] = rm1;
            pl[row0 + rA] = rl0; pl[row0 + rB] = rl1;
        }
    }
}

// ---------------------------------------------------------------------------
// out_mm, fused 4-way merge, double-buffered B, 2-CTA/SM occupancy:
// __launch_bounds__(256,2) + A-frags re-read from smem (no register hoist).
// ---------------------------------------------------------------------------
#define OSTG (128 * OSTR)
#define OUT_SMEM ((64*OSTR + 256 + 2*OSTG) * 4)
__global__ __launch_bounds__(256, 2) void out_mm(const float* __restrict__ bp,
                                                 float* __restrict__ out)
{
    extern __shared__ float smo[];
    float* As  = smo;                       // 64 x OSTR
    float* sc  = smo + 64 * OSTR;           // 64 x 4
    float* Bs0 = smo + 64 * OSTR + 256;     // stage 0
    float* Bs1 = Bs0 + OSTG;                // stage 1

    const int tid = threadIdx.x, lane = tid & 31, wid = tid >> 5;
    const int qr = lane >> 2, qc = lane & 3;
    const int wm = wid & 1, wn = wid >> 1;
    const int m0 = blockIdx.x * 64;

    if (tid < 64) {
        int row = m0 + tid;
        float m0v = g_pm[row], m1v = g_pm[MT + row], m2v = g_pm[2*MT + row], m3v = g_pm[3*MT + row];
        float mm = fmaxf(fmaxf(m0v, m1v), fmaxf(m2v, m3v));
        float e0 = __expf(m0v - mm), e1 = __expf(m1v - mm);
        float e2 = __expf(m2v - mm), e3 = __expf(m3v - mm);
        float il = 1.f / (g_pl[row] * e0 + g_pl[MT + row] * e1 +
                          g_pl[2*MT + row] * e2 + g_pl[3*MT + row] * e3);
        sc[tid * 4 + 0] = e0 * il; sc[tid * 4 + 1] = e1 * il;
        sc[tid * 4 + 2] = e2 * il; sc[tid * 4 + 3] = e3 * il;
    }
    __syncthreads();

    #pragma unroll
    for (int it = 0; it < 4; it++) {
        int gi = it * 256 + tid;
        int r = gi >> 4, q = gi & 15;
        size_t base = (size_t)(m0 + r) * HSZ + q * 4;
        float w0 = sc[r * 4 + 0], w1 = sc[r * 4 + 1], w2 = sc[r * 4 + 2], w3 = sc[r * 4 + 3];
        float4 a = *(const float4*)&g_po[base];
        float4 b = *(const float4*)&g_po[(size_t)MT * HSZ + base];
        float4 c = *(const float4*)&g_po[(size_t)2 * MT * HSZ + base];
        float4 d4 = *(const float4*)&g_po[(size_t)3 * MT * HSZ + base];
        float v0 = a.x*w0 + b.x*w1 + c.x*w2 + d4.x*w3;
        float v1 = a.y*w0 + b.y*w1 + c.y*w2 + d4.y*w3;
        float v2 = a.z*w0 + b.z*w1 + c.z*w2 + d4.z*w3;
        float v3 = a.w*w0 + b.w*w1 + c.w*w2 + d4.w*w3;
        uint32_t* s = (uint32_t*)&As[r * OSTR + (q >> 1) * 8 + (q & 1)];
        s[0] = f2tf(v0); s[2] = f2tf(v1); s[4] = f2tf(v2); s[6] = f2tf(v3);
    }

    float4 bR[8];
    #pragma unroll
    for (int i = 0; i < 8; i++) {
        int id = i * 256 + tid, r = id >> 4, q = id & 15;
        bR[i] = *(const float4*)&g_wpsumT[(size_t)r * HSZ + q * 4];
    }
    __syncthreads();

    // STS B tile 0 -> stage 0; load tile 1 -> regs
    #pragma unroll
    for (int i = 0; i < 8; i++) {
        int id = i * 256 + tid, r = id >> 4, q = id & 15;
        uint32_t* s = (uint32_t*)&Bs0[r * OSTR + (q >> 1) * 8 + (q & 1)];
        s[0] = f2tf(bR[i].x); s[2] = f2tf(bR[i].y);
        s[4] = f2tf(bR[i].z); s[6] = f2tf(bR[i].w);
    }
    #pragma unroll
    for (int i = 0; i < 8; i++) {
        int id = i * 256 + tid, r = id >> 4, q = id & 15;
        bR[i] = *(const float4*)&g_wpsumT[(size_t)(128 + r) * HSZ + q * 4];
    }
    __syncthreads();

    for (int nt = 0; nt < 8; nt++) {
        const int n0 = nt * 128;
        float* S = (nt & 1) ? Bs1 : Bs0;

        if (nt < 7) {
            float* D = (nt & 1) ? Bs0 : Bs1;
            #pragma unroll
            for (int i = 0; i < 8; i++) {
                int id = i * 256 + tid, r = id >> 4, q = id & 15;
                uint32_t* s = (uint32_t*)&D[r * OSTR + (q >> 1) * 8 + (q & 1)];
                s[0] = f2tf(bR[i].x); s[2] = f2tf(bR[i].y);
                s[4] = f2tf(bR[i].z); s[6] = f2tf(bR[i].w);
            }
            if (nt < 6) {
                #pragma unroll
                for (int i = 0; i < 8; i++) {
                    int id = i * 256 + tid, r = id >> 4, q = id & 15;
                    bR[i] = *(const float4*)&g_wpsumT[(size_t)(n0 + 256 + r) * HSZ + q * 4];
                }
            }
        }

        float d[2][4][4] = {};
        #pragma unroll
        for (int kk = 0; kk < 8; kk++) {
            // A frags from smem (saves 64 regs -> 2 CTAs/SM)
            uint32_t af[2][4];
            #pragma unroll
            for (int mi = 0; mi < 2; mi++) {
                uint2 lo = *(const uint2*)&As[(wm * 32 + mi * 16 + qr) * OSTR + kk * 8 + 2 * qc];
                uint2 hi = *(const uint2*)&As[(wm * 32 + mi * 16 + qr + 8) * OSTR + kk * 8 + 2 * qc];
                af[mi][0] = lo.x; af[mi][1] = hi.x;
                af[mi][2] = lo.y; af[mi][3] = hi.y;
            }
            #pragma unroll
            for (int ni = 0; ni < 4; ni++) {
                uint2 bf = *(const uint2*)&S[(wn * 32 + ni * 8 + qr) * OSTR + kk * 8 + 2 * qc];
                mma1688(d[0][ni], af[0][0], af[0][1], af[0][2], af[0][3], bf.x, bf.y);
                mma1688(d[1][ni], af[1][0], af[1][1], af[1][2], af[1][3], bf.x, bf.y);
            }
        }

        #pragma unroll
        for (int mi = 0; mi < 2; mi++) {
            #pragma unroll
            for (int ni = 0; ni < 4; ni++) {
                int n = n0 + wn * 32 + ni * 8 + 2 * qc;
                float2 b2 = *(const float2*)&bp[n];
                int r = m0 + wm * 32 + mi * 16 + qr;
                *(float2*)&out[(size_t)r * EE + n] =
                    make_float2(d[mi][ni][0] + b2.x, d[mi][ni][1] + b2.y);
                *(float2*)&out[(size_t)(r + 8) * EE + n] =
                    make_float2(d[mi][ni][2] + b2.x, d[mi][ni][3] + b2.y);
            }
        }
        __syncthreads();
    }
}

// ---------------------------------------------------------------------------
extern "C" void kernel_launch(void* const* d_in, const int* in_sizes, int n_in,
                              void* d_out, int out_size)
{
    const float* x  = (const float*)d_in[0];
    const float* Wq = (const float*)d_in[1];
    const float* Wk = (const float*)d_in[2];
    const float* Wv = (const float*)d_in[3];
    const float* Wp = (const float*)d_in[4];
    const float* bp = (const float*)d_in[5];
    float* out = (float*)d_out;

    cudaFuncSetAttribute(attn_mma, cudaFuncAttributeMaxDynamicSharedMemorySize, ATTN_SMEM);
    cudaFuncSetAttribute(qkv_mm,   cudaFuncAttributeMaxDynamicSharedMemorySize, QKV_SMEM);
    cudaFuncSetAttribute(out_mm,   cudaFuncAttributeMaxDynamicSharedMemorySize, OUT_SMEM);

    prep_kernel<<<832, 256>>>(Wq, Wk, Wv, Wp);
    qkv_mm<<<dim3(128, 2), 256, QKV_SMEM>>>(x);
    qkv_add<<<128, 256>>>();
    attn_mma<<<dim3(16, BB, 4), 128, ATTN_SMEM>>>();
    out_mm<<<128, 256, OUT_SMEM>>>(bp, out);
}

// round 15
// speedup vs baseline: 1.0197x; 1.0086x over previous
#include <cuda_runtime.h>
#include <math.h>
#include <stdint.h>

#define BB 4
#define TT 2048
#define EE 1024
#define HSZ 64
#define NHEAD 16
#define MT (BB*TT)

// Scratch (allocation-free rule: device globals)
// g_q: [MT][64] tf32, hs-cols fragment-permuted, PRE-SCALED by 0.125 (exact pow2)
// g_k: [MT][64] tf32, hs-cols fragment-permuted
// g_v: [BB][64][2048] = v^T per batch, token-cols fragment-permuted, tf32
__device__ float g_q[MT*HSZ];
__device__ float g_k[MT*HSZ];
__device__ float g_v[MT*HSZ];
__device__ float g_wt[192*EE];        // packed [n][k]: Wq^T | Wk^T | Wv^T
__device__ float g_wpsumT[EE*HSZ];    // [f][h] = sum_n Wp[n*64+h][f]
__device__ float g_qkvp[2*MT*192];    // qkv split-K(2) partials
__device__ float g_po[4*MT*HSZ];      // attn split-k partial O (unnormalized)
__device__ float g_pm[4*MT];          // attn partial row max
__device__ float g_pl[4*MT];          // attn partial row sum

// ---------------- HMMA helpers (baseline PTX, no 'a'-suffix features) -------
__device__ __forceinline__ uint32_t f2tf(float f) {
    uint32_t r; asm("cvt.rna.tf32.f32 %0, %1;" : "=r"(r) : "f"(f)); return r;
}
__device__ __forceinline__ float f2tff(float f) { return __uint_as_float(f2tf(f)); }
__device__ __forceinline__ void mma1688(float d[4], uint32_t a0, uint32_t a1,
                                        uint32_t a2, uint32_t a3,
                                        uint32_t b0, uint32_t b1) {
    asm volatile(
        "mma.sync.aligned.m16n8k8.row.col.f32.tf32.tf32.f32 "
        "{%0,%1,%2,%3},{%4,%5,%6,%7},{%8,%9},{%0,%1,%2,%3};"
        : "+f"(d[0]), "+f"(d[1]), "+f"(d[2]), "+f"(d[3])
        : "r"(a0), "r"(a1), "r"(a2), "r"(a3), "r"(b0), "r"(b1));
}
__device__ __forceinline__ uint32_t smem_u32(const void* p) {
    uint32_t a;
    asm("{ .reg .u64 t; cvta.to.shared.u64 t, %1; cvt.u32.u64 %0, t; }" : "=r"(a) : "l"(p));
    return a;
}
#define CP16(dst, src) asm volatile("cp.async.cg.shared.global [%0], [%1], 16;" :: "r"(dst), "l"(src) : "memory")
#define CP_COMMIT()    asm volatile("cp.async.commit_group;" ::: "memory")
#define CP_WAIT0()     asm volatile("cp.async.wait_group 0;" ::: "memory")

#define ASTR 36   // GEMM smem row stride for K=32 tiles
#define OSTR 68   // out_mm smem row stride for K=64 tiles

// ---------------------------------------------------------------------------
// prep (fused): blocks 0..767 pack W^T; 768..831 wpsumT (coalesced).  (R12)
// ---------------------------------------------------------------------------
__global__ __launch_bounds__(256) void prep_kernel(const float* __restrict__ Wq,
                                                   const float* __restrict__ Wk,
                                                   const float* __restrict__ Wv,
                                                   const float* __restrict__ Wp)
{
    __shared__ float st[64 * 20];
    int bx = blockIdx.x, tid = threadIdx.x;
    if (bx < 768) {
        int idx = bx * 256 + tid;
        int n = idx >> 10, k = idx & 1023;
        float v = (n < 64) ? Wq[k * 64 + n] : (n < 128) ? Wk[k * 64 + (n - 64)] : Wv[k * 64 + (n - 128)];
        g_wt[idx] = v;
        return;
    }
    const int f0 = (bx - 768) * 16;
    {
        int sub = tid >> 6, h = tid & 63;
        float4 s = make_float4(0.f, 0.f, 0.f, 0.f);
        #pragma unroll
        for (int n = 0; n < 16; n++) {
            float4 v = *(const float4*)&Wp[(size_t)(n * 64 + h) * EE + f0 + sub * 4];
            s.x += v.x; s.y += v.y; s.z += v.z; s.w += v.w;
        }
        *(float4*)&st[h * 20 + sub * 4] = s;
    }
    __syncthreads();
    {
        int fl = tid >> 4, h4 = (tid & 15) * 4;
        float4 o = make_float4(st[(h4 + 0) * 20 + fl], st[(h4 + 1) * 20 + fl],
                               st[(h4 + 2) * 20 + fl], st[(h4 + 3) * 20 + fl]);
        *(float4*)&g_wpsumT[(size_t)(f0 + fl) * HSZ + h4] = o;
    }
}

// ---------------------------------------------------------------------------
// qkv via HMMA tf32, SPLIT-K(2), 2-stage smem pipeline.  (R12, proven)
// ---------------------------------------------------------------------------
#define QSTG 9216
#define QKV_SMEM (2 * QSTG * 4)
__global__ __launch_bounds__(256) void qkv_mm(const float* __restrict__ x)
{
    extern __shared__ float smq[];

    const int tid = threadIdx.x, lane = tid & 31, wid = tid >> 5;
    const int qr = lane >> 2, qc = lane & 3;
    const int wm = wid & 1, wn = wid >> 1;
    const int m0 = blockIdx.x * 64;
    const int kbase = blockIdx.y * 512;

    const int fr2 = tid >> 3, fkq = tid & 7;

    float4 aR[2], bR[6];

    #pragma unroll
    for (int i = 0; i < 2; i++) {
        int r = i * 32 + fr2;
        aR[i] = *(const float4*)&x[(size_t)(m0 + r) * EE + kbase + fkq * 4];
    }
    #pragma unroll
    for (int i = 0; i < 6; i++) {
        int r = i * 32 + fr2;
        bR[i] = *(const float4*)&g_wt[(size_t)r * EE + kbase + fkq * 4];
    }
    {
        float* D = smq;
        #pragma unroll
        for (int i = 0; i < 2; i++) {
            int r = i * 32 + fr2;
            uint32_t* s = (uint32_t*)&D[r * ASTR + (fkq >> 1) * 8 + (fkq & 1)];
            s[0] = f2tf(aR[i].x); s[2] = f2tf(aR[i].y);
            s[4] = f2tf(aR[i].z); s[6] = f2tf(aR[i].w);
        }
        #pragma unroll
        for (int i = 0; i < 6; i++) {
            int r = i * 32 + fr2;
            uint32_t* s = (uint32_t*)&D[2304 + r * ASTR + (fkq >> 1) * 8 + (fkq & 1)];
            s[0] = f2tf(bR[i].x); s[2] = f2tf(bR[i].y);
            s[4] = f2tf(bR[i].z); s[6] = f2tf(bR[i].w);
        }
    }
    #pragma unroll
    for (int i = 0; i < 2; i++) {
        int r = i * 32 + fr2;
        aR[i] = *(const float4*)&x[(size_t)(m0 + r) * EE + kbase + 32 + fkq * 4];
    }
    #pragma unroll
    for (int i = 0; i < 6; i++) {
        int r = i * 32 + fr2;
        bR[i] = *(const float4*)&g_wt[(size_t)r * EE + kbase + 32 + fkq * 4];
    }
    __syncthreads();

    float d[2][6][4] = {};

    for (int kt = 0; kt < 16; kt++) {
        float* S = smq + (kt & 1) * QSTG;

        if (kt < 15) {
            float* D = smq + ((kt & 1) ^ 1) * QSTG;
            #pragma unroll
            for (int i = 0; i < 2; i++) {
                int r = i * 32 + fr2;
                uint32_t* s = (uint32_t*)&D[r * ASTR + (fkq >> 1) * 8 + (fkq & 1)];
                s[0] = f2tf(aR[i].x); s[2] = f2tf(aR[i].y);
                s[4] = f2tf(aR[i].z); s[6] = f2tf(aR[i].w);
            }
            #pragma unroll
            for (int i = 0; i < 6; i++) {
                int r = i * 32 + fr2;
                uint32_t* s = (uint32_t*)&D[2304 + r * ASTR + (fkq >> 1) * 8 + (fkq & 1)];
                s[0] = f2tf(bR[i].x); s[2] = f2tf(bR[i].y);
                s[4] = f2tf(bR[i].z); s[6] = f2tf(bR[i].w);
            }
            if (kt < 14) {
                int k0 = kbase + (kt + 2) * 32;
                #pragma unroll
                for (int i = 0; i < 2; i++) {
                    int r = i * 32 + fr2;
                    aR[i] = *(const float4*)&x[(size_t)(m0 + r) * EE + k0 + fkq * 4];
                }
                #pragma unroll
                for (int i = 0; i < 6; i++) {
                    int r = i * 32 + fr2;
                    bR[i] = *(const float4*)&g_wt[(size_t)r * EE + k0 + fkq * 4];
                }
            }
        }

        #pragma unroll
        for (int g = 0; g < 4; g++) {
            uint32_t af[2][4];
            #pragma unroll
            for (int mi = 0; mi < 2; mi++) {
                uint2 lo = *(const uint2*)&S[(wm * 32 + mi * 16 + qr) * ASTR + g * 8 + 2 * qc];
                uint2 hi = *(const uint2*)&S[(wm * 32 + mi * 16 + qr + 8) * ASTR + g * 8 + 2 * qc];
                af[mi][0] = lo.x; af[mi][1] = hi.x; af[mi][2] = lo.y; af[mi][3] = hi.y;
            }
            #pragma unroll
            for (int ni = 0; ni < 6; ni++) {
                uint2 bf = *(const uint2*)&S[2304 + (wn * 48 + ni * 8 + qr) * ASTR + g * 8 + 2 * qc];
                mma1688(d[0][ni], af[0][0], af[0][1], af[0][2], af[0][3], bf.x, bf.y);
                mma1688(d[1][ni], af[1][0], af[1][1], af[1][2], af[1][3], bf.x, bf.y);
            }
        }
        __syncthreads();
    }

    float* pp = g_qkvp + (size_t)blockIdx.y * MT * 192;
    #pragma unroll
    for (int mi = 0; mi < 2; mi++) {
        #pragma unroll
        for (int ni = 0; ni < 6; ni++) {
            int n = wn * 48 + ni * 8 + 2 * qc;
            int r = m0 + wm * 32 + mi * 16 + qr;
            *(float2*)&pp[(size_t)r * 192 + n]       = make_float2(d[mi][ni][0], d[mi][ni][1]);
            *(float2*)&pp[(size_t)(r + 8) * 192 + n] = make_float2(d[mi][ni][2], d[mi][ni][3]);
        }
    }
}

// ---------------------------------------------------------------------------
// qkv_add: sum 2 split-K partials, tf32 round, fragment permutes, q pre-scale.
// (R12, proven)
// ---------------------------------------------------------------------------
__global__ __launch_bounds__(256) void qkv_add()
{
    __shared__ float vt[64 * 68];
    const int tid = threadIdx.x;
    const int m0 = blockIdx.x * 64;
    const float* p0 = g_qkvp;
    const float* p1 = g_qkvp + (size_t)MT * 192;

    #pragma unroll
    for (int it = 0; it < 4; it++) {
        int gi = it * 256 + tid;
        int r = gi >> 4, grp = gi & 15;
        size_t base = (size_t)(m0 + r) * 192 + grp * 8;
        float sc = (grp < 8) ? 0.125f : 1.0f;
        float4 a0 = *(const float4*)&p0[base],     a1 = *(const float4*)&p0[base + 4];
        float4 b0 = *(const float4*)&p1[base],     b1 = *(const float4*)&p1[base + 4];
        float s0 = f2tff((a0.x + b0.x) * sc), s1 = f2tff((a0.y + b0.y) * sc);
        float s2 = f2tff((a0.z + b0.z) * sc), s3 = f2tff((a0.w + b0.w) * sc);
        float s4 = f2tff((a1.x + b1.x) * sc), s5 = f2tff((a1.y + b1.y) * sc);
        float s6 = f2tff((a1.z + b1.z) * sc), s7 = f2tff((a1.w + b1.w) * sc);
        float* dst = (grp < 8) ? g_q : g_k;
        int col = (grp & 7) * 8;
        *(float4*)&dst[(size_t)(m0 + r) * HSZ + col]     = make_float4(s0, s4, s1, s5);
        *(float4*)&dst[(size_t)(m0 + r) * HSZ + col + 4] = make_float4(s2, s6, s3, s7);
    }

    #pragma unroll
    for (int it = 0; it < 4; it++) {
        int gi = it * 256 + tid;
        int r = gi >> 4, c4 = (gi & 15) * 4;
        size_t base = (size_t)(m0 + r) * 192 + 128 + c4;
        float4 a = *(const float4*)&p0[base];
        float4 b = *(const float4*)&p1[base];
        *(float4*)&vt[r * 68 + c4] = make_float4(f2tff(a.x + b.x), f2tff(a.y + b.y),
                                                 f2tff(a.z + b.z), f2tff(a.w + b.w));
    }
    __syncthreads();

    int batch = m0 >> 11, tokb = m0 & 2047;
    #pragma unroll
    for (int it = 0; it < 4; it++) {
        int gi = it * 256 + tid;
        int h = gi >> 4, u = gi & 15;
        int g8 = (u >> 1) * 8, lo = u & 1;
        int c0 = g8 + (lo ? 2 : 0), c1 = g8 + (lo ? 6 : 4);
        int c2 = g8 + (lo ? 3 : 1), c3 = g8 + (lo ? 7 : 5);
        float4 o = make_float4(vt[c0 * 68 + h], vt[c1 * 68 + h],
                               vt[c2 * 68 + h], vt[c3 * 68 + h]);
        *(float4*)&g_v[(size_t)(batch * 64 + h) * 2048 + tokb + u * 4] = o;
    }
}

// ---------------------------------------------------------------------------
// Flash attention via HMMA tf32, SPLIT-K(4), Bq=64, warp-local softmax.
// (R12, proven at 28.2us)
// ---------------------------------------------------------------------------
#define ATTN_SMEM 108544
__global__ __launch_bounds__(128, 2) void attn_mma()
{
    extern __shared__ float sma[];
    float* Qs  = sma;
    float* KbS = sma + 4352;
    float* VbS = sma + 13568;
    float* Pw  = sma + 22784;

    const int b = blockIdx.y;
    const int chunk = blockIdx.z;
    const int tid = threadIdx.x, lane = tid & 31, w = tid >> 5;
    const int g = lane >> 2, t = lane & 3;
    const int rr = tid >> 4, cc4 = (tid & 15) * 4;
    const int rA = w * 16 + g, rB = rA + 8;
    float* Pu = Pw + w * 1088;

    const int p0i = 2 * ((2 * t) & 3) + ((2 * t) >> 2);
    const int p1i = 2 * ((2 * t + 1) & 3) + ((2 * t + 1) >> 2);

    const float* qb  = g_q + (size_t)b * TT * HSZ;
    const float* kb  = g_k + (size_t)b * TT * HSZ;
    const float* vtb = g_v + (size_t)b * HSZ * TT;
    float* po = g_po + (size_t)chunk * MT * HSZ + (size_t)b * TT * HSZ;
    float* pm = g_pm + (size_t)chunk * MT + (size_t)b * TT;
    float* pl = g_pl + (size_t)chunk * MT + (size_t)b * TT;

    const uint32_t sQ = smem_u32(Qs), sK = smem_u32(KbS), sV = smem_u32(VbS);

    for (int half = 0; half < 2; half++) {
        const int qt   = half ? (31 - (int)blockIdx.x) : (int)blockIdx.x;
        const int row0 = qt * 64;
        const int nkt  = qt + 1;
        const int jb   = (chunk * nkt) >> 2;
        const int je   = ((chunk + 1) * nkt) >> 2;

        if (jb == je) {
            if (tid < 64) { pm[row0 + tid] = -INFINITY; pl[row0 + tid] = 0.f; }
            continue;
        }

        __syncthreads();
        #pragma unroll
        for (int p = 0; p < 8; p++) {
            int r = p * 8 + rr;
            CP16(sQ + (uint32_t)(r * 68 + cc4) * 4, &qb[(size_t)(row0 + r) * HSZ + cc4]);
        }
        {
            int t0 = jb * 64;
            #pragma unroll
            for (int p = 0; p < 8; p++) {
                int r = p * 8 + rr;
                CP16(sK + (uint32_t)(r * 72 + cc4) * 4, &kb[(size_t)(t0 + r) * HSZ + cc4]);
                CP16(sV + (uint32_t)(r * 72 + cc4) * 4, &vtb[(size_t)r * 2048 + t0 + cc4]);
            }
        }
        CP_COMMIT();
        CP_WAIT0();
        __syncthreads();

        uint32_t qf[8][4];
        #pragma unroll
        for (int kk = 0; kk < 8; kk++) {
            uint2 u0 = *(const uint2*)&Qs[rA * 68 + kk * 8 + 2 * t];
            uint2 u1 = *(const uint2*)&Qs[rB * 68 + kk * 8 + 2 * t];
            qf[kk][0] = u0.x; qf[kk][2] = u0.y;
            qf[kk][1] = u1.x; qf[kk][3] = u1.y;
        }

        float oa[8][4] = {};
        float rm0 = -INFINITY, rm1 = -INFINITY, rl0 = 0.f, rl1 = 0.f;

        for (int j = jb; j < je; j++) {
            const int bsel = (j - jb) & 1;
            const float* Ks = KbS + bsel * 4608;
            const float* Vs = VbS + bsel * 4608;
            if (j > jb) { CP_WAIT0(); __syncthreads(); }

            if (j + 1 < je) {
                int t0n = (j + 1) * 64;
                uint32_t dK = sK + (uint32_t)((bsel ^ 1) * 4608) * 4;
                uint32_t dV = sV + (uint32_t)((bsel ^ 1) * 4608) * 4;
                #pragma unroll
                for (int p = 0; p < 8; p++) {
                    int r = p * 8 + rr;
                    CP16(dK + (uint32_t)(r * 72 + cc4) * 4, &kb[(size_t)(t0n + r) * HSZ + cc4]);
                    CP16(dV + (uint32_t)(r * 72 + cc4) * 4, &vtb[(size_t)r * 2048 + t0n + cc4]);
                }
                CP_COMMIT();
            }

            float sa[8][4] = {};
            #pragma unroll
            for (int kk = 0; kk < 8; kk++) {
                #pragma unroll
                for (int f = 0; f < 8; f++) {
                    uint2 bv = *(const uint2*)&Ks[(f * 8 + g) * 72 + kk * 8 + 2 * t];
                    mma1688(sa[f], qf[kk][0], qf[kk][1], qf[kk][2], qf[kk][3], bv.x, bv.y);
                }
            }

            const bool diag = (j == nkt - 1);
            const int t0 = j * 64;
            if (diag) {
                #pragma unroll
                for (int f = 0; f < 8; f++) {
                    int col = t0 + f * 8 + 2 * t;
                    int gA = row0 + rA, gB = row0 + rB;
                    if (col     > gA) sa[f][0] = -INFINITY;
                    if (col + 1 > gA) sa[f][1] = -INFINITY;
                    if (col     > gB) sa[f][2] = -INFINITY;
                    if (col + 1 > gB) sa[f][3] = -INFINITY;
                }
            }
            float pm0 = fmaxf(sa[0][0], sa[0][1]), pm1 = fmaxf(sa[0][2], sa[0][3]);
            #pragma unroll
            for (int f = 1; f < 8; f++) {
                pm0 = fmaxf(pm0, fmaxf(sa[f][0], sa[f][1]));
                pm1 = fmaxf(pm1, fmaxf(sa[f][2], sa[f][3]));
            }
            pm0 = fmaxf(pm0, __shfl_xor_sync(0xffffffffu, pm0, 1));
            pm0 = fmaxf(pm0, __shfl_xor_sync(0xffffffffu, pm0, 2));
            pm1 = fmaxf(pm1, __shfl_xor_sync(0xffffffffu, pm1, 1));
            pm1 = fmaxf(pm1, __shfl_xor_sync(0xffffffffu, pm1, 2));
            float mn0 = fmaxf(rm0, pm0), mn1 = fmaxf(rm1, pm1);
            float al0 = __expf(rm0 - mn0), al1 = __expf(rm1 - mn1);

            float ps0 = 0.f, ps1 = 0.f;
            #pragma unroll
            for (int f = 0; f < 8; f++) {
                float e0 = __expf(sa[f][0] - mn0), e1 = __expf(sa[f][1] - mn0);
                float e2 = __expf(sa[f][2] - mn1), e3 = __expf(sa[f][3] - mn1);
                ps0 += e0 + e1; ps1 += e2 + e3;
                Pu[g * 68 + f * 8 + p0i]       = f2tff(e0);
                Pu[g * 68 + f * 8 + p1i]       = f2tff(e1);
                Pu[(g + 8) * 68 + f * 8 + p0i] = f2tff(e2);
                Pu[(g + 8) * 68 + f * 8 + p1i] = f2tff(e3);
            }
            ps0 += __shfl_xor_sync(0xffffffffu, ps0, 1);
            ps0 += __shfl_xor_sync(0xffffffffu, ps0, 2);
            ps1 += __shfl_xor_sync(0xffffffffu, ps1, 1);
            ps1 += __shfl_xor_sync(0xffffffffu, ps1, 2);
            rl0 = rl0 * al0 + ps0;
            rl1 = rl1 * al1 + ps1;
            rm0 = mn0; rm1 = mn1;
            #pragma unroll
            for (int f = 0; f < 8; f++) {
                oa[f][0] *= al0; oa[f][1] *= al0;
                oa[f][2] *= al1; oa[f][3] *= al1;
            }
            __syncwarp();

            #pragma unroll
            for (int kk = 0; kk < 8; kk++) {
                uint2 a02 = *(const uint2*)&Pu[g * 68 + kk * 8 + 2 * t];
                uint2 a13 = *(const uint2*)&Pu[(g + 8) * 68 + kk * 8 + 2 * t];
                #pragma unroll
                for (int f = 0; f < 8; f++) {
                    uint2 bv = *(const uint2*)&Vs[(f * 8 + g) * 72 + kk * 8 + 2 * t];
                    mma1688(oa[f], a02.x, a13.x, a02.y, a13.y, bv.x, bv.y);
                }
            }
        }

        #pragma unroll
        for (int f = 0; f < 8; f++) {
            int col = f * 8 + 2 * t;
            *(float2*)&po[(size_t)(row0 + rA) * HSZ + col] = make_float2(oa[f][0], oa[f][1]);
            *(float2*)&po[(size_t)(row0 + rB) * HSZ + col] = make_float2(oa[f][2], oa[f][3]);
        }
        if (t == 0) {
            pm[row0 + rA] = rm0; pm[row0 + rB] = rm1;
            pl[row0 + rA] = rl0; pl[row0 + rB] = rl1;
        }
    }
}

// ---------------------------------------------------------------------------
// out_mm, fused 4-way merge, double-buffered B, grid (128,2) + 2 CTA/SM:
// 256 CTAs -> SMs host 2 CTAs -> B-chain latency overlapped.
// A-frags re-read from smem (regs <= 128 for the occupancy bound).
// ---------------------------------------------------------------------------
#define OSTG (128 * OSTR)
#define OUT_SMEM ((64*OSTR + 256 + 2*OSTG) * 4)
__global__ __launch_bounds__(256, 2) void out_mm(const float* __restrict__ bp,
                                                 float* __restrict__ out)
{
    extern __shared__ float smo[];
    float* As  = smo;                       // 64 x OSTR
    float* sc  = smo + 64 * OSTR;           // 64 x 4
    float* Bs0 = smo + 64 * OSTR + 256;     // stage 0
    float* Bs1 = Bs0 + OSTG;                // stage 1

    const int tid = threadIdx.x, lane = tid & 31, wid = tid >> 5;
    const int qr = lane >> 2, qc = lane & 3;
    const int wm = wid & 1, wn = wid >> 1;
    const int m0 = blockIdx.x * 64;
    const int ntb = blockIdx.y * 4;         // this CTA's first n-tile (of 8)

    if (tid < 64) {
        int row = m0 + tid;
        float m0v = g_pm[row], m1v = g_pm[MT + row], m2v = g_pm[2*MT + row], m3v = g_pm[3*MT + row];
        float mm = fmaxf(fmaxf(m0v, m1v), fmaxf(m2v, m3v));
        float e0 = __expf(m0v - mm), e1 = __expf(m1v - mm);
        float e2 = __expf(m2v - mm), e3 = __expf(m3v - mm);
        float il = 1.f / (g_pl[row] * e0 + g_pl[MT + row] * e1 +
                          g_pl[2*MT + row] * e2 + g_pl[3*MT + row] * e3);
        sc[tid * 4 + 0] = e0 * il; sc[tid * 4 + 1] = e1 * il;
        sc[tid * 4 + 2] = e2 * il; sc[tid * 4 + 3] = e3 * il;
    }
    __syncthreads();

    #pragma unroll
    for (int it = 0; it < 4; it++) {
        int gi = it * 256 + tid;
        int r = gi >> 4, q = gi & 15;
        size_t base = (size_t)(m0 + r) * HSZ + q * 4;
        float w0 = sc[r * 4 + 0], w1 = sc[r * 4 + 1], w2 = sc[r * 4 + 2], w3 = sc[r * 4 + 3];
        float4 a = *(const float4*)&g_po[base];
        float4 b = *(const float4*)&g_po[(size_t)MT * HSZ + base];
        float4 c = *(const float4*)&g_po[(size_t)2 * MT * HSZ + base];
        float4 d4 = *(const float4*)&g_po[(size_t)3 * MT * HSZ + base];
        float v0 = a.x*w0 + b.x*w1 + c.x*w2 + d4.x*w3;
        float v1 = a.y*w0 + b.y*w1 + c.y*w2 + d4.y*w3;
        float v2 = a.z*w0 + b.z*w1 + c.z*w2 + d4.z*w3;
        float v3 = a.w*w0 + b.w*w1 + c.w*w2 + d4.w*w3;
        uint32_t* s = (uint32_t*)&As[r * OSTR + (q >> 1) * 8 + (q & 1)];
        s[0] = f2tf(v0); s[2] = f2tf(v1); s[4] = f2tf(v2); s[6] = f2tf(v3);
    }

    float4 bR[8];
    #pragma unroll
    for (int i = 0; i < 8; i++) {
        int id = i * 256 + tid, r = id >> 4, q = id & 15;
        bR[i] = *(const float4*)&g_wpsumT[(size_t)(ntb * 128 + r) * HSZ + q * 4];
    }
    __syncthreads();

    // STS B tile ntb -> stage 0; load tile ntb+1 -> regs
    #pragma unroll
    for (int i = 0; i < 8; i++) {
        int id = i * 256 + tid, r = id >> 4, q = id & 15;
        uint32_t* s = (uint32_t*)&Bs0[r * OSTR + (q >> 1) * 8 + (q & 1)];
        s[0] = f2tf(bR[i].x); s[2] = f2tf(bR[i].y);
        s[4] = f2tf(bR[i].z); s[6] = f2tf(bR[i].w);
    }
    #pragma unroll
    for (int i = 0; i < 8; i++) {
        int id = i * 256 + tid, r = id >> 4, q = id & 15;
        bR[i] = *(const float4*)&g_wpsumT[(size_t)((ntb + 1) * 128 + r) * HSZ + q * 4];
    }
    __syncthreads();

    for (int ti = 0; ti < 4; ti++) {
        const int nt = ntb + ti;
        const int n0 = nt * 128;
        float* S = (ti & 1) ? Bs1 : Bs0;

        if (ti < 3) {
            float* D = (ti & 1) ? Bs0 : Bs1;
            #pragma unroll
            for (int i = 0; i < 8; i++) {
                int id = i * 256 + tid, r = id >> 4, q = id & 15;
                uint32_t* s = (uint32_t*)&D[r * OSTR + (q >> 1) * 8 + (q & 1)];
                s[0] = f2tf(bR[i].x); s[2] = f2tf(bR[i].y);
                s[4] = f2tf(bR[i].z); s[6] = f2tf(bR[i].w);
            }
            if (ti < 2) {
                #pragma unroll
                for (int i = 0; i < 8; i++) {
                    int id = i * 256 + tid, r = id >> 4, q = id & 15;
                    bR[i] = *(const float4*)&g_wpsumT[(size_t)(n0 + 256 + r) * HSZ + q * 4];
                }
            }
        }

        float d[2][4][4] = {};
        #pragma unroll
        for (int kk = 0; kk < 8; kk++) {
            uint32_t af[2][4];
            #pragma unroll
            for (int mi = 0; mi < 2; mi++) {
                uint2 lo = *(const uint2*)&As[(wm * 32 + mi * 16 + qr) * OSTR + kk * 8 + 2 * qc];
                uint2 hi = *(const uint2*)&As[(wm * 32 + mi * 16 + qr + 8) * OSTR + kk * 8 + 2 * qc];
                af[mi][0] = lo.x; af[mi][1] = hi.x;
                af[mi][2] = lo.y; af[mi][3] = hi.y;
            }
            #pragma unroll
            for (int ni = 0; ni < 4; ni++) {
                uint2 bf = *(const uint2*)&S[(wn * 32 + ni * 8 + qr) * OSTR + kk * 8 + 2 * qc];
                mma1688(d[0][ni], af[0][0], af[0][1], af[0][2], af[0][3], bf.x, bf.y);
                mma1688(d[1][ni], af[1][0], af[1][1], af[1][2], af[1][3], bf.x, bf.y);
            }
        }

        #pragma unroll
        for (int mi = 0; mi < 2; mi++) {
            #pragma unroll
            for (int ni = 0; ni < 4; ni++) {
                int n = n0 + wn * 32 + ni * 8 + 2 * qc;
                float2 b2 = *(const float2*)&bp[n];
                int r = m0 + wm * 32 + mi * 16 + qr;
                *(float2*)&out[(size_t)r * EE + n] =
                    make_float2(d[mi][ni][0] + b2.x, d[mi][ni][1] + b2.y);
                *(float2*)&out[(size_t)(r + 8) * EE + n] =
                    make_float2(d[mi][ni][2] + b2.x, d[mi][ni][3] + b2.y);
            }
        }
        __syncthreads();
    }
}

// ---------------------------------------------------------------------------
extern "C" void kernel_launch(void* const* d_in, const int* in_sizes, int n_in,
                              void* d_out, int out_size)
{
    const float* x  = (const float*)d_in[0];
    const float* Wq = (const float*)d_in[1];
    const float* Wk = (const float*)d_in[2];
    const float* Wv = (const float*)d_in[3];
    const float* Wp = (const float*)d_in[4];
    const float* bp = (const float*)d_in[5];
    float* out = (float*)d_out;

    cudaFuncSetAttribute(attn_mma, cudaFuncAttributeMaxDynamicSharedMemorySize, ATTN_SMEM);
    cudaFuncSetAttribute(qkv_mm,   cudaFuncAttributeMaxDynamicSharedMemorySize, QKV_SMEM);
    cudaFuncSetAttribute(out_mm,   cudaFuncAttributeMaxDynamicSharedMemorySize, OUT_SMEM);

    prep_kernel<<<832, 256>>>(Wq, Wk, Wv, Wp);
    qkv_mm<<<dim3(128, 2), 256, QKV_SMEM>>>(x);
    qkv_add<<<128, 256>>>();
    attn_mma<<<dim3(16, BB, 4), 128, ATTN_SMEM>>>();
    out_mm<<<dim3(128, 2), 256, OUT_SMEM>>>(bp, out);
}

// round 16
// speedup vs baseline: 1.0408x; 1.0207x over previous
#include <cuda_runtime.h>
#include <math.h>
#include <stdint.h>

#define BB 4
#define TT 2048
#define EE 1024
#define HSZ 64
#define NHEAD 16
#define MT (BB*TT)

// Scratch (allocation-free rule: device globals)
// g_q: [MT][64] tf32, hs-cols fragment-permuted, PRE-SCALED by 0.125 (exact pow2)
// g_k: [MT][64] tf32, hs-cols fragment-permuted
// g_v: [BB][64][2048] = v^T per batch, token-cols fragment-permuted, tf32
__device__ float g_q[MT*HSZ];
__device__ float g_k[MT*HSZ];
__device__ float g_v[MT*HSZ];
__device__ float g_wt[192*EE];        // packed [n][k]: Wq^T | Wk^T | Wv^T
__device__ float g_wpsumT[EE*HSZ];    // [f][h] = sum_n Wp[n*64+h][f]
__device__ float g_qkvp[2*MT*192];    // qkv split-K(2) partials
__device__ float g_po[4*MT*HSZ];      // attn split-k partial O (unnormalized)
__device__ float g_pm[4*MT];          // attn partial row max
__device__ float g_pl[4*MT];          // attn partial row sum

// ---------------- HMMA helpers (baseline PTX, no 'a'-suffix features) -------
__device__ __forceinline__ uint32_t f2tf(float f) {
    uint32_t r; asm("cvt.rna.tf32.f32 %0, %1;" : "=r"(r) : "f"(f)); return r;
}
__device__ __forceinline__ float f2tff(float f) { return __uint_as_float(f2tf(f)); }
__device__ __forceinline__ void mma1688(float d[4], uint32_t a0, uint32_t a1,
                                        uint32_t a2, uint32_t a3,
                                        uint32_t b0, uint32_t b1) {
    asm volatile(
        "mma.sync.aligned.m16n8k8.row.col.f32.tf32.tf32.f32 "
        "{%0,%1,%2,%3},{%4,%5,%6,%7},{%8,%9},{%0,%1,%2,%3};"
        : "+f"(d[0]), "+f"(d[1]), "+f"(d[2]), "+f"(d[3])
        : "r"(a0), "r"(a1), "r"(a2), "r"(a3), "r"(b0), "r"(b1));
}
__device__ __forceinline__ uint32_t smem_u32(const void* p) {
    uint32_t a;
    asm("{ .reg .u64 t; cvta.to.shared.u64 t, %1; cvt.u32.u64 %0, t; }" : "=r"(a) : "l"(p));
    return a;
}
#define CP16(dst, src) asm volatile("cp.async.cg.shared.global [%0], [%1], 16;" :: "r"(dst), "l"(src) : "memory")
#define CP_COMMIT()    asm volatile("cp.async.commit_group;" ::: "memory")
#define CP_WAIT0()     asm volatile("cp.async.wait_group 0;" ::: "memory")

#define ASTR 36   // GEMM smem row stride for K=32 tiles
#define OSTR 68   // out_mm smem row stride for K=64 tiles

// ---------------------------------------------------------------------------
// prep (fused): blocks 0..767 pack W^T; 768..831 wpsumT (coalesced).  (R12)
// ---------------------------------------------------------------------------
__global__ __launch_bounds__(256) void prep_kernel(const float* __restrict__ Wq,
                                                   const float* __restrict__ Wk,
                                                   const float* __restrict__ Wv,
                                                   const float* __restrict__ Wp)
{
    __shared__ float st[64 * 20];
    int bx = blockIdx.x, tid = threadIdx.x;
    if (bx < 768) {
        int idx = bx * 256 + tid;
        int n = idx >> 10, k = idx & 1023;
        float v = (n < 64) ? Wq[k * 64 + n] : (n < 128) ? Wk[k * 64 + (n - 64)] : Wv[k * 64 + (n - 128)];
        g_wt[idx] = v;
        return;
    }
    const int f0 = (bx - 768) * 16;
    {
        int sub = tid >> 6, h = tid & 63;
        float4 s = make_float4(0.f, 0.f, 0.f, 0.f);
        #pragma unroll
        for (int n = 0; n < 16; n++) {
            float4 v = *(const float4*)&Wp[(size_t)(n * 64 + h) * EE + f0 + sub * 4];
            s.x += v.x; s.y += v.y; s.z += v.z; s.w += v.w;
        }
        *(float4*)&st[h * 20 + sub * 4] = s;
    }
    __syncthreads();
    {
        int fl = tid >> 4, h4 = (tid & 15) * 4;
        float4 o = make_float4(st[(h4 + 0) * 20 + fl], st[(h4 + 1) * 20 + fl],
                               st[(h4 + 2) * 20 + fl], st[(h4 + 3) * 20 + fl]);
        *(float4*)&g_wpsumT[(size_t)(f0 + fl) * HSZ + h4] = o;
    }
}

// ---------------------------------------------------------------------------
// qkv via HMMA tf32, SPLIT-K(2), 2-stage smem pipeline.  (R12, proven)
// ---------------------------------------------------------------------------
#define QSTG 9216
#define QKV_SMEM (2 * QSTG * 4)
__global__ __launch_bounds__(256) void qkv_mm(const float* __restrict__ x)
{
    extern __shared__ float smq[];

    const int tid = threadIdx.x, lane = tid & 31, wid = tid >> 5;
    const int qr = lane >> 2, qc = lane & 3;
    const int wm = wid & 1, wn = wid >> 1;
    const int m0 = blockIdx.x * 64;
    const int kbase = blockIdx.y * 512;

    const int fr2 = tid >> 3, fkq = tid & 7;

    float4 aR[2], bR[6];

    #pragma unroll
    for (int i = 0; i < 2; i++) {
        int r = i * 32 + fr2;
        aR[i] = *(const float4*)&x[(size_t)(m0 + r) * EE + kbase + fkq * 4];
    }
    #pragma unroll
    for (int i = 0; i < 6; i++) {
        int r = i * 32 + fr2;
        bR[i] = *(const float4*)&g_wt[(size_t)r * EE + kbase + fkq * 4];
    }
    {
        float* D = smq;
        #pragma unroll
        for (int i = 0; i < 2; i++) {
            int r = i * 32 + fr2;
            uint32_t* s = (uint32_t*)&D[r * ASTR + (fkq >> 1) * 8 + (fkq & 1)];
            s[0] = f2tf(aR[i].x); s[2] = f2tf(aR[i].y);
            s[4] = f2tf(aR[i].z); s[6] = f2tf(aR[i].w);
        }
        #pragma unroll
        for (int i = 0; i < 6; i++) {
            int r = i * 32 + fr2;
            uint32_t* s = (uint32_t*)&D[2304 + r * ASTR + (fkq >> 1) * 8 + (fkq & 1)];
            s[0] = f2tf(bR[i].x); s[2] = f2tf(bR[i].y);
            s[4] = f2tf(bR[i].z); s[6] = f2tf(bR[i].w);
        }
    }
    #pragma unroll
    for (int i = 0; i < 2; i++) {
        int r = i * 32 + fr2;
        aR[i] = *(const float4*)&x[(size_t)(m0 + r) * EE + kbase + 32 + fkq * 4];
    }
    #pragma unroll
    for (int i = 0; i < 6; i++) {
        int r = i * 32 + fr2;
        bR[i] = *(const float4*)&g_wt[(size_t)r * EE + kbase + 32 + fkq * 4];
    }
    __syncthreads();

    float d[2][6][4] = {};

    for (int kt = 0; kt < 16; kt++) {
        float* S = smq + (kt & 1) * QSTG;

        if (kt < 15) {
            float* D = smq + ((kt & 1) ^ 1) * QSTG;
            #pragma unroll
            for (int i = 0; i < 2; i++) {
                int r = i * 32 + fr2;
                uint32_t* s = (uint32_t*)&D[r * ASTR + (fkq >> 1) * 8 + (fkq & 1)];
                s[0] = f2tf(aR[i].x); s[2] = f2tf(aR[i].y);
                s[4] = f2tf(aR[i].z); s[6] = f2tf(aR[i].w);
            }
            #pragma unroll
            for (int i = 0; i < 6; i++) {
                int r = i * 32 + fr2;
                uint32_t* s = (uint32_t*)&D[2304 + r * ASTR + (fkq >> 1) * 8 + (fkq & 1)];
                s[0] = f2tf(bR[i].x); s[2] = f2tf(bR[i].y);
                s[4] = f2tf(bR[i].z); s[6] = f2tf(bR[i].w);
            }
            if (kt < 14) {
                int k0 = kbase + (kt + 2) * 32;
                #pragma unroll
                for (int i = 0; i < 2; i++) {
                    int r = i * 32 + fr2;
                    aR[i] = *(const float4*)&x[(size_t)(m0 + r) * EE + k0 + fkq * 4];
                }
                #pragma unroll
                for (int i = 0; i < 6; i++) {
                    int r = i * 32 + fr2;
                    bR[i] = *(const float4*)&g_wt[(size_t)r * EE + k0 + fkq * 4];
                }
            }
        }

        #pragma unroll
        for (int g = 0; g < 4; g++) {
            uint32_t af[2][4];
            #pragma unroll
            for (int mi = 0; mi < 2; mi++) {
                uint2 lo = *(const uint2*)&S[(wm * 32 + mi * 16 + qr) * ASTR + g * 8 + 2 * qc];
                uint2 hi = *(const uint2*)&S[(wm * 32 + mi * 16 + qr + 8) * ASTR + g * 8 + 2 * qc];
                af[mi][0] = lo.x; af[mi][1] = hi.x; af[mi][2] = lo.y; af[mi][3] = hi.y;
            }
            #pragma unroll
            for (int ni = 0; ni < 6; ni++) {
                uint2 bf = *(const uint2*)&S[2304 + (wn * 48 + ni * 8 + qr) * ASTR + g * 8 + 2 * qc];
                mma1688(d[0][ni], af[0][0], af[0][1], af[0][2], af[0][3], bf.x, bf.y);
                mma1688(d[1][ni], af[1][0], af[1][1], af[1][2], af[1][3], bf.x, bf.y);
            }
        }
        __syncthreads();
    }

    float* pp = g_qkvp + (size_t)blockIdx.y * MT * 192;
    #pragma unroll
    for (int mi = 0; mi < 2; mi++) {
        #pragma unroll
        for (int ni = 0; ni < 6; ni++) {
            int n = wn * 48 + ni * 8 + 2 * qc;
            int r = m0 + wm * 32 + mi * 16 + qr;
            *(float2*)&pp[(size_t)r * 192 + n]       = make_float2(d[mi][ni][0], d[mi][ni][1]);
            *(float2*)&pp[(size_t)(r + 8) * 192 + n] = make_float2(d[mi][ni][2], d[mi][ni][3]);
        }
    }
}

// ---------------------------------------------------------------------------
// qkv_add: sum 2 split-K partials, tf32 round, fragment permutes, q pre-scale.
// (R12, proven)
// ---------------------------------------------------------------------------
__global__ __launch_bounds__(256) void qkv_add()
{
    __shared__ float vt[64 * 68];
    const int tid = threadIdx.x;
    const int m0 = blockIdx.x * 64;
    const float* p0 = g_qkvp;
    const float* p1 = g_qkvp + (size_t)MT * 192;

    #pragma unroll
    for (int it = 0; it < 4; it++) {
        int gi = it * 256 + tid;
        int r = gi >> 4, grp = gi & 15;
        size_t base = (size_t)(m0 + r) * 192 + grp * 8;
        float sc = (grp < 8) ? 0.125f : 1.0f;
        float4 a0 = *(const float4*)&p0[base],     a1 = *(const float4*)&p0[base + 4];
        float4 b0 = *(const float4*)&p1[base],     b1 = *(const float4*)&p1[base + 4];
        float s0 = f2tff((a0.x + b0.x) * sc), s1 = f2tff((a0.y + b0.y) * sc);
        float s2 = f2tff((a0.z + b0.z) * sc), s3 = f2tff((a0.w + b0.w) * sc);
        float s4 = f2tff((a1.x + b1.x) * sc), s5 = f2tff((a1.y + b1.y) * sc);
        float s6 = f2tff((a1.z + b1.z) * sc), s7 = f2tff((a1.w + b1.w) * sc);
        float* dst = (grp < 8) ? g_q : g_k;
        int col = (grp & 7) * 8;
        *(float4*)&dst[(size_t)(m0 + r) * HSZ + col]     = make_float4(s0, s4, s1, s5);
        *(float4*)&dst[(size_t)(m0 + r) * HSZ + col + 4] = make_float4(s2, s6, s3, s7);
    }

    #pragma unroll
    for (int it = 0; it < 4; it++) {
        int gi = it * 256 + tid;
        int r = gi >> 4, c4 = (gi & 15) * 4;
        size_t base = (size_t)(m0 + r) * 192 + 128 + c4;
        float4 a = *(const float4*)&p0[base];
        float4 b = *(const float4*)&p1[base];
        *(float4*)&vt[r * 68 + c4] = make_float4(f2tff(a.x + b.x), f2tff(a.y + b.y),
                                                 f2tff(a.z + b.z), f2tff(a.w + b.w));
    }
    __syncthreads();

    int batch = m0 >> 11, tokb = m0 & 2047;
    #pragma unroll
    for (int it = 0; it < 4; it++) {
        int gi = it * 256 + tid;
        int h = gi >> 4, u = gi & 15;
        int g8 = (u >> 1) * 8, lo = u & 1;
        int c0 = g8 + (lo ? 2 : 0), c1 = g8 + (lo ? 6 : 4);
        int c2 = g8 + (lo ? 3 : 1), c3 = g8 + (lo ? 7 : 5);
        float4 o = make_float4(vt[c0 * 68 + h], vt[c1 * 68 + h],
                               vt[c2 * 68 + h], vt[c3 * 68 + h]);
        *(float4*)&g_v[(size_t)(batch * 64 + h) * 2048 + tokb + u * 4] = o;
    }
}

// ---------------------------------------------------------------------------
// Flash attention via HMMA tf32, SPLIT-K(4), Bq=64, warp-local softmax.
// SINGLE KV buffer -> smem 71680 B -> 3 CTAs/SM; __launch_bounds__(128,3).
// Load latency exposed per-iter, hidden by cross-CTA overlap (12 warps/SM).
// ---------------------------------------------------------------------------
#define ATTN_SMEM 71680
__global__ __launch_bounds__(128, 3) void attn_mma()
{
    extern __shared__ float sma[];
    float* Qs = sma;                  // 64*68 = 4352
    float* Ks = sma + 4352;           // 64*72
    float* Vs = sma + 8960;           // 64*72
    float* Pw = sma + 13568;          // 4 x 16*68

    const int b = blockIdx.y;
    const int chunk = blockIdx.z;
    const int tid = threadIdx.x, lane = tid & 31, w = tid >> 5;
    const int g = lane >> 2, t = lane & 3;
    const int rr = tid >> 4, cc4 = (tid & 15) * 4;
    const int rA = w * 16 + g, rB = rA + 8;
    float* Pu = Pw + w * 1088;

    const int p0i = 2 * ((2 * t) & 3) + ((2 * t) >> 2);
    const int p1i = 2 * ((2 * t + 1) & 3) + ((2 * t + 1) >> 2);

    const float* qb  = g_q + (size_t)b * TT * HSZ;
    const float* kb  = g_k + (size_t)b * TT * HSZ;
    const float* vtb = g_v + (size_t)b * HSZ * TT;
    float* po = g_po + (size_t)chunk * MT * HSZ + (size_t)b * TT * HSZ;
    float* pm = g_pm + (size_t)chunk * MT + (size_t)b * TT;
    float* pl = g_pl + (size_t)chunk * MT + (size_t)b * TT;

    const uint32_t sQ = smem_u32(Qs), sK = smem_u32(Ks), sV = smem_u32(Vs);

    for (int half = 0; half < 2; half++) {
        const int qt   = half ? (31 - (int)blockIdx.x) : (int)blockIdx.x;
        const int row0 = qt * 64;
        const int nkt  = qt + 1;
        const int jb   = (chunk * nkt) >> 2;
        const int je   = ((chunk + 1) * nkt) >> 2;

        if (jb == je) {
            if (tid < 64) { pm[row0 + tid] = -INFINITY; pl[row0 + tid] = 0.f; }
            continue;
        }

        __syncthreads();                       // prev half done with smem
        #pragma unroll
        for (int p = 0; p < 8; p++) {          // Q tile
            int r = p * 8 + rr;
            CP16(sQ + (uint32_t)(r * 68 + cc4) * 4, &qb[(size_t)(row0 + r) * HSZ + cc4]);
        }
        CP_COMMIT();
        CP_WAIT0();
        __syncthreads();

        uint32_t qf[8][4];
        #pragma unroll
        for (int kk = 0; kk < 8; kk++) {
            uint2 u0 = *(const uint2*)&Qs[rA * 68 + kk * 8 + 2 * t];
            uint2 u1 = *(const uint2*)&Qs[rB * 68 + kk * 8 + 2 * t];
            qf[kk][0] = u0.x; qf[kk][2] = u0.y;
            qf[kk][1] = u1.x; qf[kk][3] = u1.y;
        }

        float oa[8][4] = {};
        float rm0 = -INFINITY, rm1 = -INFINITY, rl0 = 0.f, rl1 = 0.f;

        for (int j = jb; j < je; j++) {
            const int t0 = j * 64;
            __syncthreads();                   // all warps done reading prev KV
            #pragma unroll
            for (int p = 0; p < 8; p++) {      // KV tile j
                int r = p * 8 + rr;
                CP16(sK + (uint32_t)(r * 72 + cc4) * 4, &kb[(size_t)(t0 + r) * HSZ + cc4]);
                CP16(sV + (uint32_t)(r * 72 + cc4) * 4, &vtb[(size_t)r * 2048 + t0 + cc4]);
            }
            CP_COMMIT();
            CP_WAIT0();
            __syncthreads();                   // KV visible

            float sa[8][4] = {};
            #pragma unroll
            for (int kk = 0; kk < 8; kk++) {
                #pragma unroll
                for (int f = 0; f < 8; f++) {
                    uint2 bv = *(const uint2*)&Ks[(f * 8 + g) * 72 + kk * 8 + 2 * t];
                    mma1688(sa[f], qf[kk][0], qf[kk][1], qf[kk][2], qf[kk][3], bv.x, bv.y);
                }
            }

            const bool diag = (j == nkt - 1);
            if (diag) {
                #pragma unroll
                for (int f = 0; f < 8; f++) {
                    int col = t0 + f * 8 + 2 * t;
                    int gA = row0 + rA, gB = row0 + rB;
                    if (col     > gA) sa[f][0] = -INFINITY;
                    if (col + 1 > gA) sa[f][1] = -INFINITY;
                    if (col     > gB) sa[f][2] = -INFINITY;
                    if (col + 1 > gB) sa[f][3] = -INFINITY;
                }
            }
            float pm0 = fmaxf(sa[0][0], sa[0][1]), pm1 = fmaxf(sa[0][2], sa[0][3]);
            #pragma unroll
            for (int f = 1; f < 8; f++) {
                pm0 = fmaxf(pm0, fmaxf(sa[f][0], sa[f][1]));
                pm1 = fmaxf(pm1, fmaxf(sa[f][2], sa[f][3]));
            }
            pm0 = fmaxf(pm0, __shfl_xor_sync(0xffffffffu, pm0, 1));
            pm0 = fmaxf(pm0, __shfl_xor_sync(0xffffffffu, pm0, 2));
            pm1 = fmaxf(pm1, __shfl_xor_sync(0xffffffffu, pm1, 1));
            pm1 = fmaxf(pm1, __shfl_xor_sync(0xffffffffu, pm1, 2));
            float mn0 = fmaxf(rm0, pm0), mn1 = fmaxf(rm1, pm1);
            float al0 = __expf(rm0 - mn0), al1 = __expf(rm1 - mn1);

            float ps0 = 0.f, ps1 = 0.f;
            #pragma unroll
            for (int f = 0; f < 8; f++) {
                float e0 = __expf(sa[f][0] - mn0), e1 = __expf(sa[f][1] - mn0);
                float e2 = __expf(sa[f][2] - mn1), e3 = __expf(sa[f][3] - mn1);
                ps0 += e0 + e1; ps1 += e2 + e3;
                Pu[g * 68 + f * 8 + p0i]       = f2tff(e0);
                Pu[g * 68 + f * 8 + p1i]       = f2tff(e1);
                Pu[(g + 8) * 68 + f * 8 + p0i] = f2tff(e2);
                Pu[(g + 8) * 68 + f * 8 + p1i] = f2tff(e3);
            }
            ps0 += __shfl_xor_sync(0xffffffffu, ps0, 1);
            ps0 += __shfl_xor_sync(0xffffffffu, ps0, 2);
            ps1 += __shfl_xor_sync(0xffffffffu, ps1, 1);
            ps1 += __shfl_xor_sync(0xffffffffu, ps1, 2);
            rl0 = rl0 * al0 + ps0;
            rl1 = rl1 * al1 + ps1;
            rm0 = mn0; rm1 = mn1;
            #pragma unroll
            for (int f = 0; f < 8; f++) {
                oa[f][0] *= al0; oa[f][1] *= al0;
                oa[f][2] *= al1; oa[f][3] *= al1;
            }
            __syncwarp();

            #pragma unroll
            for (int kk = 0; kk < 8; kk++) {
                uint2 a02 = *(const uint2*)&Pu[g * 68 + kk * 8 + 2 * t];
                uint2 a13 = *(const uint2*)&Pu[(g + 8) * 68 + kk * 8 + 2 * t];
                #pragma unroll
                for (int f = 0; f < 8; f++) {
                    uint2 bv = *(const uint2*)&Vs[(f * 8 + g) * 72 + kk * 8 + 2 * t];
                    mma1688(oa[f], a02.x, a13.x, a02.y, a13.y, bv.x, bv.y);
                }
            }
        }

        #pragma unroll
        for (int f = 0; f < 8; f++) {
            int col = f * 8 + 2 * t;
            *(float2*)&po[(size_t)(row0 + rA) * HSZ + col] = make_float2(oa[f][0], oa[f][1]);
            *(float2*)&po[(size_t)(row0 + rB) * HSZ + col] = make_float2(oa[f][2], oa[f][3]);
        }
        if (t == 0) {
            pm[row0 + rA] = rm0; pm[row0 + rB] = rm1;
            pl[row0 + rA] = rl0; pl[row0 + rB] = rl1;
        }
    }
}

// ---------------------------------------------------------------------------
// out_mm, fused 4-way merge, double-buffered B tiles (R12 version, grid 128).
// ---------------------------------------------------------------------------
#define OSTG (128 * OSTR)
#define OUT_SMEM ((64*OSTR + 256 + 2*OSTG) * 4)
__global__ __launch_bounds__(256) void out_mm(const float* __restrict__ bp,
                                              float* __restrict__ out)
{
    extern __shared__ float smo[];
    float* As  = smo;                       // 64 x OSTR
    float* sc  = smo + 64 * OSTR;           // 64 x 4
    float* Bs0 = smo + 64 * OSTR + 256;     // stage 0
    float* Bs1 = Bs0 + OSTG;                // stage 1

    const int tid = threadIdx.x, lane = tid & 31, wid = tid >> 5;
    const int qr = lane >> 2, qc = lane & 3;
    const int wm = wid & 1, wn = wid >> 1;
    const int m0 = blockIdx.x * 64;

    if (tid < 64) {
        int row = m0 + tid;
        float m0v = g_pm[row], m1v = g_pm[MT + row], m2v = g_pm[2*MT + row], m3v = g_pm[3*MT + row];
        float mm = fmaxf(fmaxf(m0v, m1v), fmaxf(m2v, m3v));
        float e0 = __expf(m0v - mm), e1 = __expf(m1v - mm);
        float e2 = __expf(m2v - mm), e3 = __expf(m3v - mm);
        float il = 1.f / (g_pl[row] * e0 + g_pl[MT + row] * e1 +
                          g_pl[2*MT + row] * e2 + g_pl[3*MT + row] * e3);
        sc[tid * 4 + 0] = e0 * il; sc[tid * 4 + 1] = e1 * il;
        sc[tid * 4 + 2] = e2 * il; sc[tid * 4 + 3] = e3 * il;
    }
    __syncthreads();

    #pragma unroll
    for (int it = 0; it < 4; it++) {
        int gi = it * 256 + tid;
        int r = gi >> 4, q = gi & 15;
        size_t base = (size_t)(m0 + r) * HSZ + q * 4;
        float w0 = sc[r * 4 + 0], w1 = sc[r * 4 + 1], w2 = sc[r * 4 + 2], w3 = sc[r * 4 + 3];
        float4 a = *(const float4*)&g_po[base];
        float4 b = *(const float4*)&g_po[(size_t)MT * HSZ + base];
        float4 c = *(const float4*)&g_po[(size_t)2 * MT * HSZ + base];
        float4 d4 = *(const float4*)&g_po[(size_t)3 * MT * HSZ + base];
        float v0 = a.x*w0 + b.x*w1 + c.x*w2 + d4.x*w3;
        float v1 = a.y*w0 + b.y*w1 + c.y*w2 + d4.y*w3;
        float v2 = a.z*w0 + b.z*w1 + c.z*w2 + d4.z*w3;
        float v3 = a.w*w0 + b.w*w1 + c.w*w2 + d4.w*w3;
        uint32_t* s = (uint32_t*)&As[r * OSTR + (q >> 1) * 8 + (q & 1)];
        s[0] = f2tf(v0); s[2] = f2tf(v1); s[4] = f2tf(v2); s[6] = f2tf(v3);
    }

    float4 bR[8];
    #pragma unroll
    for (int i = 0; i < 8; i++) {
        int id = i * 256 + tid, r = id >> 4, q = id & 15;
        bR[i] = *(const float4*)&g_wpsumT[(size_t)r * HSZ + q * 4];
    }
    __syncthreads();

    uint32_t af[2][8][4];
    #pragma unroll
    for (int kk = 0; kk < 8; kk++) {
        #pragma unroll
        for (int mi = 0; mi < 2; mi++) {
            uint2 lo = *(const uint2*)&As[(wm * 32 + mi * 16 + qr) * OSTR + kk * 8 + 2 * qc];
            uint2 hi = *(const uint2*)&As[(wm * 32 + mi * 16 + qr + 8) * OSTR + kk * 8 + 2 * qc];
            af[mi][kk][0] = lo.x; af[mi][kk][1] = hi.x;
            af[mi][kk][2] = lo.y; af[mi][kk][3] = hi.y;
        }
    }

    #pragma unroll
    for (int i = 0; i < 8; i++) {
        int id = i * 256 + tid, r = id >> 4, q = id & 15;
        uint32_t* s = (uint32_t*)&Bs0[r * OSTR + (q >> 1) * 8 + (q & 1)];
        s[0] = f2tf(bR[i].x); s[2] = f2tf(bR[i].y);
        s[4] = f2tf(bR[i].z); s[6] = f2tf(bR[i].w);
    }
    #pragma unroll
    for (int i = 0; i < 8; i++) {
        int id = i * 256 + tid, r = id >> 4, q = id & 15;
        bR[i] = *(const float4*)&g_wpsumT[(size_t)(128 + r) * HSZ + q * 4];
    }
    __syncthreads();

    for (int nt = 0; nt < 8; nt++) {
        const int n0 = nt * 128;
        float* S = (nt & 1) ? Bs1 : Bs0;

        if (nt < 7) {
            float* D = (nt & 1) ? Bs0 : Bs1;
            #pragma unroll
            for (int i = 0; i < 8; i++) {
                int id = i * 256 + tid, r = id >> 4, q = id & 15;
                uint32_t* s = (uint32_t*)&D[r * OSTR + (q >> 1) * 8 + (q & 1)];
                s[0] = f2tf(bR[i].x); s[2] = f2tf(bR[i].y);
                s[4] = f2tf(bR[i].z); s[6] = f2tf(bR[i].w);
            }
            if (nt < 6) {
                #pragma unroll
                for (int i = 0; i < 8; i++) {
                    int id = i * 256 + tid, r = id >> 4, q = id & 15;
                    bR[i] = *(const float4*)&g_wpsumT[(size_t)(n0 + 256 + r) * HSZ + q * 4];
                }
            }
        }

        float d[2][4][4] = {};
        #pragma unroll
        for (int kk = 0; kk < 8; kk++) {
            #pragma unroll
            for (int ni = 0; ni < 4; ni++) {
                uint2 bf = *(const uint2*)&S[(wn * 32 + ni * 8 + qr) * OSTR + kk * 8 + 2 * qc];
                mma1688(d[0][ni], af[0][kk][0], af[0][kk][1], af[0][kk][2], af[0][kk][3], bf.x, bf.y);
                mma1688(d[1][ni], af[1][kk][0], af[1][kk][1], af[1][kk][2], af[1][kk][3], bf.x, bf.y);
            }
        }

        #pragma unroll
        for (int mi = 0; mi < 2; mi++) {
            #pragma unroll
            for (int ni = 0; ni < 4; ni++) {
                int n = n0 + wn * 32 + ni * 8 + 2 * qc;
                float2 b2 = *(const float2*)&bp[n];
                int r = m0 + wm * 32 + mi * 16 + qr;
                *(float2*)&out[(size_t)r * EE + n] =
                    make_float2(d[mi][ni][0] + b2.x, d[mi][ni][1] + b2.y);
                *(float2*)&out[(size_t)(r + 8) * EE + n] =
                    make_float2(d[mi][ni][2] + b2.x, d[mi][ni][3] + b2.y);
            }
        }
        __syncthreads();
    }
}

// ---------------------------------------------------------------------------
extern "C" void kernel_launch(void* const* d_in, const int* in_sizes, int n_in,
                              void* d_out, int out_size)
{
    const float* x  = (const float*)d_in[0];
    const float* Wq = (const float*)d_in[1];
    const float* Wk = (const float*)d_in[2];
    const float* Wv = (const float*)d_in[3];
    const float* Wp = (const float*)d_in[4];
    const float* bp = (const float*)d_in[5];
    float* out = (float*)d_out;

    cudaFuncSetAttribute(attn_mma, cudaFuncAttributeMaxDynamicSharedMemorySize, ATTN_SMEM);
    cudaFuncSetAttribute(qkv_mm,   cudaFuncAttributeMaxDynamicSharedMemorySize, QKV_SMEM);
    cudaFuncSetAttribute(out_mm,   cudaFuncAttributeMaxDynamicSharedMemorySize, OUT_SMEM);

    prep_kernel<<<832, 256>>>(Wq, Wk, Wv, Wp);
    qkv_mm<<<dim3(128, 2), 256, QKV_SMEM>>>(x);
    qkv_add<<<128, 256>>>();
    attn_mma<<<dim3(16, BB, 4), 128, ATTN_SMEM>>>();
    out_mm<<<128, 256, OUT_SMEM>>>(bp, out);
}